// round 8
// baseline (speedup 1.0000x reference)
#include <cuda_runtime.h>
#include <cuda_fp16.h>
#include <math.h>
#include <stdint.h>

#define Bq 2
#define Sq 2048
#define Dq 512
#define Hq 8

#define SDc  ((long)Sq * Dq)
#define SSc  ((long)Sq * Sq)
#define DDc  ((long)Dq * Dq)

#define X_PLANE    ((long)Bq * Sq * Dq)
#define W_PLANE    ((long)Hq * Dq * Dq)
#define QK_PLANE   ((long)Bq * Hq * Sq * Dq)
#define ATTN_PLANE ((long)Bq * Hq * Sq * Sq)
#define Z_PLANE    QK_PLANE

__device__ __align__(256) float g_attn[ATTN_PLANE];
__device__ __align__(256) __half g_xq [2 * X_PLANE];
__device__ __align__(256) __half g_xk [2 * X_PLANE];
__device__ __align__(256) __half g_xv [2 * X_PLANE];
__device__ __align__(256) __half g_wqt[2 * W_PLANE];
__device__ __align__(256) __half g_wkt[2 * W_PLANE];
__device__ __align__(256) __half g_wvt[2 * W_PLANE];
__device__ __align__(256) __half g_wzt[2 * W_PLANE];
__device__ __align__(256) signed char g_q8[2 * QK_PLANE];   // int8 digit planes
__device__ __align__(256) signed char g_k8[2 * QK_PLANE];
__device__ __align__(256) __half g_vts[2 * QK_PLANE];   // [b,h,e,s]
__device__ __align__(256) __half g_zs [2 * Z_PLANE];    // [b,s,h*D]
__device__ __align__(256) __half g_ps [2 * ATTN_PLANE]; // split probs (x1024)

struct Off { int dv; long s1; int md; long s2; };

__device__ __forceinline__ uint32_t smem_u32(const void* p) {
    uint32_t a;
    asm("{ .reg .u64 t; cvta.to.shared.u64 t, %1; cvt.u32.u64 %0, t; }" : "=r"(a) : "l"(p));
    return a;
}
__device__ __forceinline__ void cpasync16(uint32_t dst, const void* src) {
    asm volatile("cp.async.cg.shared.global [%0], [%1], 16;" :: "r"(dst), "l"(src) : "memory");
}
#define CP_COMMIT() asm volatile("cp.async.commit_group;" ::: "memory")
#define CP_WAIT1()  asm volatile("cp.async.wait_group 1;" ::: "memory")
#define CP_WAIT0()  asm volatile("cp.async.wait_group 0;" ::: "memory")

#define LDSM4(r, a) \
    asm volatile("ldmatrix.sync.aligned.m8n8.x4.shared.b16 {%0,%1,%2,%3}, [%4];" \
        : "=r"((r)[0]), "=r"((r)[1]), "=r"((r)[2]), "=r"((r)[3]) : "r"(a))

#define MMAF(c, a, b0, b1) \
    asm volatile("mma.sync.aligned.m16n8k16.row.col.f32.f16.f16.f32 " \
        "{%0,%1,%2,%3},{%4,%5,%6,%7},{%8,%9},{%0,%1,%2,%3};" \
        : "+f"((c)[0]), "+f"((c)[1]), "+f"((c)[2]), "+f"((c)[3]) \
        : "r"((a)[0]), "r"((a)[1]), "r"((a)[2]), "r"((a)[3]), "r"(b0), "r"(b1))

#define MMAH(c, a, b0, b1) \
    asm volatile("mma.sync.aligned.m16n8k16.row.col.f16.f16.f16.f16 " \
        "{%0,%1},{%2,%3,%4,%5},{%6,%7},{%0,%1};" \
        : "+r"((c)[0]), "+r"((c)[1]) \
        : "r"((a)[0]), "r"((a)[1]), "r"((a)[2]), "r"((a)[3]), "r"(b0), "r"(b1))

#define MMAI(c, a, b0, b1) \
    asm volatile("mma.sync.aligned.m16n8k32.row.col.s32.s8.s8.s32 " \
        "{%0,%1,%2,%3},{%4,%5,%6,%7},{%8,%9},{%0,%1,%2,%3};" \
        : "+r"((c)[0]), "+r"((c)[1]), "+r"((c)[2]), "+r"((c)[3]) \
        : "r"((a)[0]), "r"((a)[1]), "r"((a)[2]), "r"((a)[3]), "r"(b0), "r"(b1))

__device__ __forceinline__ void split1(float x, __half& h, __half& l) {
    h = __float2half_rn(x);
    l = __float2half_rn(x - __half2float(h));
}
__device__ __forceinline__ void quant2(float v, signed char& d0, signed char& d1) {
    float a = rintf(v * (1.0f / 256.0f));
    a = fminf(127.f, fmaxf(-127.f, a));
    float r = v - 256.0f * a;
    float b = fminf(127.f, fmaxf(-127.f, rintf(r)));
    d0 = (signed char)a;
    d1 = (signed char)b;
}

#define STAGE_B  16384
#define STAGE_SZ 32768
#define NSTAGE   3
#define SMEM_SZ  (NSTAGE * STAGE_SZ)
#define GTHREADS 512

// ---------------------------------------------------------------------------
// fp16 HMMA TN GEMM (unchanged from R7 except mode 3).
// mode 0: fp32 (+bias). mode 1: split-fp16. mode 2: split-fp16 transposed.
// mode 3: int8 radix-256 digit planes (alpha pre-folded with 1/s).
// ---------------------------------------------------------------------------
__global__ void __launch_bounds__(GTHREADS, 1)
gemm_mma(const __half* __restrict__ A, long aplane,
         const __half* __restrict__ B, long bplane,
         void* Cv, long cplane,
         int K, int lda, int ldb, int ldc,
         Off oa, Off ob, Off oc,
         float alpha, const float* __restrict__ bias, int mode)
{
    extern __shared__ char smem[];
    const uint32_t sm = smem_u32(smem);
    const int tid = threadIdx.x, wid = tid >> 5, lane = tid & 31;
    const int z = blockIdx.z;

    const __half* Ahp = A + (long)(z / oa.dv) * oa.s1 + (long)(z % oa.md) * oa.s2;
    const __half* Bhp = B + (long)(z / ob.dv) * ob.s1 + (long)(z % ob.md) * ob.s2;
    const long coff = (long)(z / oc.dv) * oc.s1 + (long)(z % oc.md) * oc.s2;

    const long row0 = (long)blockIdx.y * 128;
    const long col0 = (long)blockIdx.x * 128;

    const int lrow = tid >> 2;
    const int c0   = (tid & 3) * 2;
    const int lpl  = c0 >> 2;
    const __half* Asrc = (lpl ? Ahp + aplane : Ahp) + (row0 + lrow) * lda + (c0 & 3) * 8;
    const __half* Bsrc = (lpl ? Bhp + bplane : Bhp) + (col0 + lrow) * ldb + (c0 & 3) * 8;
    uint32_t soff[2];
    #pragma unroll
    for (int j = 0; j < 2; ++j)
        soff[j] = lrow * 128 + (((c0 + j) ^ (lrow & 7)) << 4);

    const int wm = wid & 3, wn = wid >> 2;
    const int g = lane >> 3, r8 = lane & 7;
    const int a_roff = ((g & 1) << 3) + r8;
    const int a_kh   = g >> 1;
    const int b_roff = ((g >> 1) << 3) + r8;
    const int b_kh   = g & 1;

    uint32_t a_row[2], a_rx[2];
    #pragma unroll
    for (int mt = 0; mt < 2; ++mt) {
        const int row = wm * 32 + mt * 16 + a_roff;
        a_row[mt] = row * 128;
        a_rx[mt] = row & 7;
    }
    uint32_t b_row[2], b_rx[2];
    #pragma unroll
    for (int np = 0; np < 2; ++np) {
        const int row = wn * 32 + np * 16 + b_roff;
        b_row[np] = row * 128;
        b_rx[np] = row & 7;
    }

    float acc[2][4][4];
    uint32_t acch[2][4][2];
    #pragma unroll
    for (int i = 0; i < 2; ++i)
        #pragma unroll
        for (int j = 0; j < 4; ++j) {
            #pragma unroll
            for (int q = 0; q < 4; ++q) acc[i][j][q] = 0.0f;
            acch[i][j][0] = 0u; acch[i][j][1] = 0u;
        }

    const int nst = K / 32;

    #pragma unroll
    for (int p = 0; p < 2; ++p) {
        if (p < nst) {
            const uint32_t tb = sm + p * STAGE_SZ;
            const long k0 = (long)p * 32;
            #pragma unroll
            for (int j = 0; j < 2; ++j) {
                cpasync16(tb + soff[j], Asrc + k0 + j * 8);
                cpasync16(tb + STAGE_B + soff[j], Bsrc + k0 + j * 8);
            }
        }
        CP_COMMIT();
    }

    int stg = 0;
    for (int s = 0; s < nst; ++s) {
        if (s + 1 < nst) CP_WAIT1(); else CP_WAIT0();
        __syncthreads();

        const uint32_t tb = sm + stg * STAGE_SZ;
        const uint32_t tba = tb, tbb = tb + STAGE_B;

        #pragma unroll
        for (int ks = 0; ks < 2; ++ks) {
            const int ca = ks * 2 + a_kh;
            const int cb = ks * 2 + b_kh;

            uint32_t Ahr[2][4], Bhr[2][4];
            #pragma unroll
            for (int mt = 0; mt < 2; ++mt)
                LDSM4(Ahr[mt], tba + a_row[mt] + ((ca ^ a_rx[mt]) << 4));
            #pragma unroll
            for (int np = 0; np < 2; ++np)
                LDSM4(Bhr[np], tbb + b_row[np] + ((cb ^ b_rx[np]) << 4));
            #pragma unroll
            for (int mt = 0; mt < 2; ++mt)
                #pragma unroll
                for (int nt = 0; nt < 4; ++nt) {
                    const int np = nt >> 1, s2 = (nt & 1) * 2;
                    MMAF(acc[mt][nt], Ahr[mt], Bhr[np][s2], Bhr[np][s2 + 1]);
                }

            uint32_t Blr[2][4];
            #pragma unroll
            for (int np = 0; np < 2; ++np)
                LDSM4(Blr[np], tbb + b_row[np] + (((cb + 4) ^ b_rx[np]) << 4));
            #pragma unroll
            for (int mt = 0; mt < 2; ++mt)
                #pragma unroll
                for (int nt = 0; nt < 4; ++nt) {
                    const int np = nt >> 1, s2 = (nt & 1) * 2;
                    MMAH(acch[mt][nt], Ahr[mt], Blr[np][s2], Blr[np][s2 + 1]);
                }

            uint32_t Alr[2][4];
            #pragma unroll
            for (int mt = 0; mt < 2; ++mt)
                LDSM4(Alr[mt], tba + a_row[mt] + (((ca + 4) ^ a_rx[mt]) << 4));
            #pragma unroll
            for (int mt = 0; mt < 2; ++mt)
                #pragma unroll
                for (int nt = 0; nt < 4; ++nt) {
                    const int np = nt >> 1, s2 = (nt & 1) * 2;
                    MMAH(acch[mt][nt], Alr[mt], Bhr[np][s2], Bhr[np][s2 + 1]);
                }
        }

        if (s + 2 < nst) {
            int ps = stg + 2; if (ps >= NSTAGE) ps -= NSTAGE;
            const uint32_t pb = sm + ps * STAGE_SZ;
            const long k0 = (long)(s + 2) * 32;
            #pragma unroll
            for (int j = 0; j < 2; ++j) {
                cpasync16(pb + soff[j], Asrc + k0 + j * 8);
                cpasync16(pb + STAGE_B + soff[j], Bsrc + k0 + j * 8);
            }
        }
        CP_COMMIT();

        if (++stg == NSTAGE) stg = 0;
    }

    const int r_in = lane >> 2, c_in = (lane & 3) * 2;
    #pragma unroll
    for (int mt = 0; mt < 2; ++mt) {
        #pragma unroll
        for (int half = 0; half < 2; ++half) {
            const long row = row0 + wm * 32 + mt * 16 + half * 8 + r_in;
            #pragma unroll
            for (int nt = 0; nt < 4; ++nt) {
                const int colg = (int)col0 + wn * 32 + nt * 8 + c_in;
                float2 cf = __half22float2(*reinterpret_cast<__half2*>(&acch[mt][nt][half]));
                float v0 = (acc[mt][nt][half * 2 + 0] + cf.x) * alpha;
                float v1 = (acc[mt][nt][half * 2 + 1] + cf.y) * alpha;
                if (mode == 0) {
                    if (bias) { v0 += bias[colg]; v1 += bias[colg + 1]; }
                    *(float2*)((float*)Cv + coff + row * ldc + colg) = make_float2(v0, v1);
                } else if (mode == 1) {
                    __half h0, l0, h1, l1;
                    split1(v0, h0, l0); split1(v1, h1, l1);
                    __half2 hh; hh.x = h0; hh.y = h1;
                    __half2 ll; ll.x = l0; ll.y = l1;
                    __half* Ch = (__half*)Cv + coff + row * ldc + colg;
                    *(__half2*)Ch = hh;
                    *(__half2*)(Ch + cplane) = ll;
                } else if (mode == 2) {
                    __half h0, l0, h1, l1;
                    split1(v0, h0, l0); split1(v1, h1, l1);
                    __half* Ch = (__half*)Cv + coff;
                    const long o0 = (long)colg * ldc + row;
                    const long o1 = (long)(colg + 1) * ldc + row;
                    Ch[o0] = h0; Ch[o0 + cplane] = l0;
                    Ch[o1] = h1; Ch[o1 + cplane] = l1;
                } else {
                    signed char d00, d01, d10, d11;
                    quant2(v0, d00, d01);
                    quant2(v1, d10, d11);
                    signed char* Ch = (signed char*)Cv + coff + row * ldc + colg;
                    Ch[0] = d00; Ch[1] = d10;
                    Ch[cplane] = d01; Ch[cplane + 1] = d11;
                }
            }
        }
    }
}

// ---------------------------------------------------------------------------
// int8 IMMA TN GEMM, radix-256 2-digit, 3 passes (d0e0 -> accA; d0e1+d1e0 -> accB).
// Block 128x128, K-chunk 64, 16 warps. Smem row: 128B = [64B d0 | 64B d1].
// Output fp32: C = c1*accA + c2*accB.
// ---------------------------------------------------------------------------
__global__ void __launch_bounds__(GTHREADS, 1)
gemm_imma(const signed char* __restrict__ A, long aplane,
          const signed char* __restrict__ B, long bplane,
          float* __restrict__ C,
          int K, int lda, int ldb, int ldc,
          Off oa, Off ob, Off oc,
          float c1, float c2)
{
    extern __shared__ char smem[];
    const uint32_t sm = smem_u32(smem);
    const int tid = threadIdx.x, wid = tid >> 5, lane = tid & 31;
    const int z = blockIdx.z;

    const signed char* A0p = A + (long)(z / oa.dv) * oa.s1 + (long)(z % oa.md) * oa.s2;
    const signed char* B0p = B + (long)(z / ob.dv) * ob.s1 + (long)(z % ob.md) * ob.s2;
    const long coff = (long)(z / oc.dv) * oc.s1 + (long)(z % oc.md) * oc.s2;

    const long row0 = (long)blockIdx.y * 128;
    const long col0 = (long)blockIdx.x * 128;

    // loader: 4 threads/row, each 2 chunks (32B). chunks 0-3 = d0 k0-63, 4-7 = d1.
    const int lrow = tid >> 2;
    const int pr   = tid & 3;
    const signed char* Asrc = (pr >= 2 ? A0p + aplane : A0p) + (row0 + lrow) * lda + (pr & 1) * 32;
    const signed char* Bsrc = (pr >= 2 ? B0p + bplane : B0p) + (col0 + lrow) * ldb + (pr & 1) * 32;
    uint32_t soff[2];
    #pragma unroll
    for (int j = 0; j < 2; ++j)
        soff[j] = lrow * 128 + (((pr * 2 + j) ^ (lrow & 7)) << 4);

    const int wm = wid & 3, wn = wid >> 2;
    const int g = lane >> 3, r8 = lane & 7;
    const int a_roff = ((g & 1) << 3) + r8;
    const int a_kh   = g >> 1;
    const int b_roff = ((g >> 1) << 3) + r8;
    const int b_kh   = g & 1;

    uint32_t a_row[2], a_rx[2];
    #pragma unroll
    for (int mt = 0; mt < 2; ++mt) {
        const int row = wm * 32 + mt * 16 + a_roff;
        a_row[mt] = row * 128;
        a_rx[mt] = row & 7;
    }
    uint32_t b_row[2], b_rx[2];
    #pragma unroll
    for (int np = 0; np < 2; ++np) {
        const int row = wn * 32 + np * 16 + b_roff;
        b_row[np] = row * 128;
        b_rx[np] = row & 7;
    }

    int accA[2][4][4], accB[2][4][4];
    #pragma unroll
    for (int i = 0; i < 2; ++i)
        #pragma unroll
        for (int j = 0; j < 4; ++j)
            #pragma unroll
            for (int q = 0; q < 4; ++q) { accA[i][j][q] = 0; accB[i][j][q] = 0; }

    const int nst = K / 64;

    #pragma unroll
    for (int p = 0; p < 2; ++p) {
        if (p < nst) {
            const uint32_t tb = sm + p * STAGE_SZ;
            const long k0 = (long)p * 64;
            #pragma unroll
            for (int j = 0; j < 2; ++j) {
                cpasync16(tb + soff[j], Asrc + k0 + j * 16);
                cpasync16(tb + STAGE_B + soff[j], Bsrc + k0 + j * 16);
            }
        }
        CP_COMMIT();
    }

    int stg = 0;
    for (int s = 0; s < nst; ++s) {
        if (s + 1 < nst) CP_WAIT1(); else CP_WAIT0();
        __syncthreads();

        const uint32_t tb = sm + stg * STAGE_SZ;
        const uint32_t tba = tb, tbb = tb + STAGE_B;

        #pragma unroll
        for (int ks = 0; ks < 2; ++ks) {
            const int ca = ks * 2 + a_kh;
            const int cb = ks * 2 + b_kh;

            // pass 1: d0 x e0 -> accA
            uint32_t A0r[2][4], B0r[2][4];
            #pragma unroll
            for (int mt = 0; mt < 2; ++mt)
                LDSM4(A0r[mt], tba + a_row[mt] + ((ca ^ a_rx[mt]) << 4));
            #pragma unroll
            for (int np = 0; np < 2; ++np)
                LDSM4(B0r[np], tbb + b_row[np] + ((cb ^ b_rx[np]) << 4));
            #pragma unroll
            for (int mt = 0; mt < 2; ++mt)
                #pragma unroll
                for (int nt = 0; nt < 4; ++nt) {
                    const int np = nt >> 1, s2 = (nt & 1) * 2;
                    MMAI(accA[mt][nt], A0r[mt], B0r[np][s2], B0r[np][s2 + 1]);
                }

            // pass 2: d0 x e1 -> accB
            uint32_t B1r[2][4];
            #pragma unroll
            for (int np = 0; np < 2; ++np)
                LDSM4(B1r[np], tbb + b_row[np] + (((cb + 4) ^ b_rx[np]) << 4));
            #pragma unroll
            for (int mt = 0; mt < 2; ++mt)
                #pragma unroll
                for (int nt = 0; nt < 4; ++nt) {
                    const int np = nt >> 1, s2 = (nt & 1) * 2;
                    MMAI(accB[mt][nt], A0r[mt], B1r[np][s2], B1r[np][s2 + 1]);
                }

            // pass 3: d1 x e0 -> accB
            uint32_t A1r[2][4];
            #pragma unroll
            for (int mt = 0; mt < 2; ++mt)
                LDSM4(A1r[mt], tba + a_row[mt] + (((ca + 4) ^ a_rx[mt]) << 4));
            #pragma unroll
            for (int mt = 0; mt < 2; ++mt)
                #pragma unroll
                for (int nt = 0; nt < 4; ++nt) {
                    const int np = nt >> 1, s2 = (nt & 1) * 2;
                    MMAI(accB[mt][nt], A1r[mt], B0r[np][s2], B0r[np][s2 + 1]);
                }
        }

        if (s + 2 < nst) {
            int ps = stg + 2; if (ps >= NSTAGE) ps -= NSTAGE;
            const uint32_t pb = sm + ps * STAGE_SZ;
            const long k0 = (long)(s + 2) * 64;
            #pragma unroll
            for (int j = 0; j < 2; ++j) {
                cpasync16(pb + soff[j], Asrc + k0 + j * 16);
                cpasync16(pb + STAGE_B + soff[j], Bsrc + k0 + j * 16);
            }
        }
        CP_COMMIT();

        if (++stg == NSTAGE) stg = 0;
    }

    const int r_in = lane >> 2, c_in = (lane & 3) * 2;
    #pragma unroll
    for (int mt = 0; mt < 2; ++mt) {
        #pragma unroll
        for (int half = 0; half < 2; ++half) {
            const long row = row0 + wm * 32 + mt * 16 + half * 8 + r_in;
            #pragma unroll
            for (int nt = 0; nt < 4; ++nt) {
                const int colg = (int)col0 + wn * 32 + nt * 8 + c_in;
                float v0 = c1 * (float)accA[mt][nt][half * 2 + 0] + c2 * (float)accB[mt][nt][half * 2 + 0];
                float v1 = c1 * (float)accA[mt][nt][half * 2 + 1] + c2 * (float)accB[mt][nt][half * 2 + 1];
                *(float2*)(C + coff + row * ldc + colg) = make_float2(v0, v1);
            }
        }
    }
}

// ---------------------------------------------------------------------------
__global__ void __launch_bounds__(256) split_kernel(const float* __restrict__ in,
                                                    __half* __restrict__ hi, long plane,
                                                    float scale)
{
    const long idx = (long)blockIdx.x * 256 + threadIdx.x;
    float4 v = ((const float4*)in)[idx];
    __half h0, l0, h1, l1, h2, l2, h3, l3;
    split1(v.x * scale, h0, l0); split1(v.y * scale, h1, l1);
    split1(v.z * scale, h2, l2); split1(v.w * scale, h3, l3);
    __half2 a, b, c, d;
    a.x = h0; a.y = h1; b.x = h2; b.y = h3;
    c.x = l0; c.y = l1; d.x = l2; d.y = l3;
    ((__half2*)hi)[2 * idx]     = a;
    ((__half2*)hi)[2 * idx + 1] = b;
    ((__half2*)(hi + plane))[2 * idx]     = c;
    ((__half2*)(hi + plane))[2 * idx + 1] = d;
}

__global__ void __launch_bounds__(256) tsplit_kernel(const float* __restrict__ in,
                                                     __half* __restrict__ outh,
                                                     long plane, int R, int C, float scale)
{
    __shared__ float ts[32][33];
    const int tx = threadIdx.x, ty = threadIdx.y;
    const long zo = (long)blockIdx.z * R * C;
    const int r0 = blockIdx.y * 32, c0 = blockIdx.x * 32;
    #pragma unroll
    for (int i = 0; i < 4; ++i)
        ts[ty + 8 * i][tx] = in[zo + (long)(r0 + ty + 8 * i) * C + c0 + tx];
    __syncthreads();
    #pragma unroll
    for (int i = 0; i < 4; ++i) {
        __half h, l;
        split1(ts[tx][ty + 8 * i] * scale, h, l);
        const long o = zo + (long)(c0 + ty + 8 * i) * R + r0 + tx;
        outh[o] = h;
        outh[o + plane] = l;
    }
}

__global__ void __launch_bounds__(256) softmax_kernel()
{
    const long rowo = (long)blockIdx.x * Sq;
    const float* p = g_attn + rowo;
    const int tid = threadIdx.x;

    float v[8];
    float mx = -1e30f;
    #pragma unroll
    for (int i = 0; i < 8; ++i) { v[i] = p[tid + i * 256]; mx = fmaxf(mx, v[i]); }
    #pragma unroll
    for (int o = 16; o > 0; o >>= 1) mx = fmaxf(mx, __shfl_xor_sync(~0u, mx, o));
    __shared__ float sr[8];
    if ((tid & 31) == 0) sr[tid >> 5] = mx;
    __syncthreads();
    float m = sr[0];
    #pragma unroll
    for (int i = 1; i < 8; ++i) m = fmaxf(m, sr[i]);
    __syncthreads();
    float s = 0.f;
    #pragma unroll
    for (int i = 0; i < 8; ++i) { v[i] = __expf(v[i] - m); s += v[i]; }
    #pragma unroll
    for (int o = 16; o > 0; o >>= 1) s += __shfl_xor_sync(~0u, s, o);
    if ((tid & 31) == 0) sr[tid >> 5] = s;
    __syncthreads();
    float t = 0.f;
    #pragma unroll
    for (int i = 0; i < 8; ++i) t += sr[i];
    const float inv = 1024.0f / t;
    #pragma unroll
    for (int i = 0; i < 8; ++i) {
        __half h, l;
        split1(v[i] * inv, h, l);
        g_ps[rowo + tid + i * 256] = h;
        g_ps[ATTN_PLANE + rowo + tid + i * 256] = l;
    }
}

__global__ void __launch_bounds__(256) avg_kernel(float* __restrict__ out)
{
    const long p2 = (long)blockIdx.x * 256 + threadIdx.x;
    const long per_b = SSc / 2;
    const long b = p2 / per_b, r = p2 % per_b;
    const __half2* hi = (const __half2*)g_ps;
    const __half2* lo = (const __half2*)(g_ps + ATTN_PLANE);
    float2 acc = make_float2(0.f, 0.f);
    #pragma unroll
    for (int h = 0; h < Hq; ++h) {
        const long o = (b * Hq + h) * per_b + r;
        float2 a = __half22float2(hi[o]);
        float2 c = __half22float2(lo[o]);
        acc.x += a.x + c.x;
        acc.y += a.y + c.y;
    }
    const float f = 1.0f / 8192.0f;
    acc.x *= f; acc.y *= f;
    ((float2*)out)[p2] = acc;
}

// ---------------------------------------------------------------------------
extern "C" void kernel_launch(void* const* d_in, const int* in_sizes, int n_in,
                              void* d_out, int out_size)
{
    (void)in_sizes; (void)n_in; (void)out_size;
    const float* Xq = (const float*)d_in[0];
    const float* Xk = (const float*)d_in[1];
    const float* Xv = (const float*)d_in[2];
    const float* Wq = (const float*)d_in[3];
    const float* Wk = (const float*)d_in[4];
    const float* Wv = (const float*)d_in[5];
    const float* Wz = (const float*)d_in[6];
    const float* bz = (const float*)d_in[7];
    float* out = (float*)d_out;
    float* attn_avg = out + (long)Bq * Sq * Dq;

    __half *pxq, *pxk, *pxv, *pwq, *pwk, *pwv, *pwz, *pvt, *pzs, *pps;
    signed char *pq8, *pk8;
    float* pattn;
    cudaGetSymbolAddress((void**)&pxq, g_xq);
    cudaGetSymbolAddress((void**)&pxk, g_xk);
    cudaGetSymbolAddress((void**)&pxv, g_xv);
    cudaGetSymbolAddress((void**)&pwq, g_wqt);
    cudaGetSymbolAddress((void**)&pwk, g_wkt);
    cudaGetSymbolAddress((void**)&pwv, g_wvt);
    cudaGetSymbolAddress((void**)&pwz, g_wzt);
    cudaGetSymbolAddress((void**)&pq8, g_q8);
    cudaGetSymbolAddress((void**)&pk8, g_k8);
    cudaGetSymbolAddress((void**)&pvt, g_vts);
    cudaGetSymbolAddress((void**)&pzs, g_zs);
    cudaGetSymbolAddress((void**)&pps, g_ps);
    cudaGetSymbolAddress((void**)&pattn, g_attn);

    cudaFuncSetAttribute(gemm_mma, cudaFuncAttributeMaxDynamicSharedMemorySize, SMEM_SZ);
    cudaFuncSetAttribute(gemm_imma, cudaFuncAttributeMaxDynamicSharedMemorySize, SMEM_SZ);

    const float inv4 = (float)(1.0 / pow((double)Dq, 0.25));
    const float SQK  = 1.5f / 32639.0f;               // int8 radix-256 quant scale
    const float alphaQK = inv4 * (1.0f / 16.0f) / SQK; // fold 1/s into proj alpha
    const float c1 = SQK * SQK * 65536.0f;
    const float c2 = SQK * SQK * 256.0f;

    // 1) split inputs; transpose+split weights
    {
        int nb = (int)(X_PLANE / 1024);
        split_kernel<<<nb, 256>>>(Xq, pxq, X_PLANE, 1.0f);
        split_kernel<<<nb, 256>>>(Xk, pxk, X_PLANE, 1.0f);
        split_kernel<<<nb, 256>>>(Xv, pxv, X_PLANE, 1.0f);
        dim3 tb(32, 8);
        tsplit_kernel<<<dim3(16, 16, 8), tb>>>(Wq, pwq, W_PLANE, Dq, Dq, 16.0f);
        tsplit_kernel<<<dim3(16, 16, 8), tb>>>(Wk, pwk, W_PLANE, Dq, Dq, 16.0f);
        tsplit_kernel<<<dim3(16, 16, 8), tb>>>(Wv, pwv, W_PLANE, Dq, Dq, 16.0f);
        tsplit_kernel<<<dim3(16, 128, 1), tb>>>(Wz, pwz, W_PLANE, Hq * Dq, Dq, 64.0f);
    }

    // 2) projections. Q,K -> int8 digit planes (mode 3); V -> fp16-split transposed.
    {
        dim3 grid(Dq / 128, Sq / 128, Bq * Hq);
        Off oa = { Hq, SDc, 1, 0 };
        Off ob = { 1, 0, Hq, DDc };
        Off oc = { 1, SDc, 1, 0 };
        gemm_mma<<<grid, GTHREADS, SMEM_SZ>>>(pxq, X_PLANE, pwq, W_PLANE, pq8, QK_PLANE,
                                              Dq, Dq, Dq, Dq, oa, ob, oc, alphaQK, nullptr, 3);
        gemm_mma<<<grid, GTHREADS, SMEM_SZ>>>(pxk, X_PLANE, pwk, W_PLANE, pk8, QK_PLANE,
                                              Dq, Dq, Dq, Dq, oa, ob, oc, alphaQK, nullptr, 3);
        gemm_mma<<<grid, GTHREADS, SMEM_SZ>>>(pxv, X_PLANE, pwv, W_PLANE, pvt, QK_PLANE,
                                              Dq, Dq, Dq, Sq, oa, ob, oc, 0.25f, nullptr, 2);
    }

    // 3) scores (fp32) via int8 IMMA: s^2*(65536*A + 256*B)
    {
        dim3 grid(Sq / 128, Sq / 128, Bq * Hq);
        Off oa = { 1, SDc, 1, 0 };
        Off ob = { 1, SDc, 1, 0 };
        Off oc = { 1, SSc, 1, 0 };
        gemm_imma<<<grid, GTHREADS, SMEM_SZ>>>(pq8, QK_PLANE, pk8, QK_PLANE, pattn,
                                               Dq, Dq, Dq, Sq, oa, ob, oc, c1, c2);
    }

    // 4) softmax -> split probs (x1024); 5) head average
    softmax_kernel<<<Bq * Hq * Sq, 256>>>();
    avg_kernel<<<(int)(Bq * SSc / 2 / 256), 256>>>(attn_avg);

    // 6) z_s = 32*z = (p_s . v_s) / 128
    {
        dim3 grid(Dq / 128, Sq / 128, Bq * Hq);
        Off oa = { 1, SSc, 1, 0 };
        Off ob = { 1, SDc, 1, 0 };
        Off oc = { Hq, (long)Sq * Hq * Dq, Hq, (long)Dq };
        gemm_mma<<<grid, GTHREADS, SMEM_SZ>>>(pps, ATTN_PLANE, pvt, QK_PLANE, pzs, Z_PLANE,
                                              Sq, Sq, Sq, Hq * Dq, oa, ob, oc, 1.0f / 128.0f, nullptr, 1);
    }

    // 7) out = (z_s . wz_s)/2048 + bz (fp32)
    {
        dim3 grid(Dq / 128, (Bq * Sq) / 128, 1);
        Off oz = { 1, 0, 1, 0 };
        gemm_mma<<<grid, GTHREADS, SMEM_SZ>>>(pzs, Z_PLANE, pwz, W_PLANE, out, 0,
                                              Hq * Dq, Hq * Dq, Hq * Dq, Dq,
                                              oz, oz, oz, 1.0f / 2048.0f, bz, 0);
    }
}

// round 9
// speedup vs baseline: 1.4938x; 1.4938x over previous
#include <cuda_runtime.h>
#include <cuda_fp16.h>
#include <math.h>
#include <stdint.h>

#define Bq 2
#define Sq 2048
#define Dq 512
#define Hq 8

#define SDc  ((long)Sq * Dq)
#define SSc  ((long)Sq * Sq)
#define DDc  ((long)Dq * Dq)

#define X_PLANE    ((long)Bq * Sq * Dq)
#define W_PLANE    ((long)Hq * Dq * Dq)
#define QK_PLANE   ((long)Bq * Hq * Sq * Dq)
#define ATTN_PLANE ((long)Bq * Hq * Sq * Sq)
#define Z_PLANE    QK_PLANE

__device__ __align__(256) float g_attn[ATTN_PLANE];
__device__ __align__(256) __half g_xq [2 * X_PLANE];
__device__ __align__(256) __half g_xk [2 * X_PLANE];
__device__ __align__(256) __half g_xv [2 * X_PLANE];
__device__ __align__(256) __half g_wqt[2 * W_PLANE];
__device__ __align__(256) __half g_wkt[2 * W_PLANE];
__device__ __align__(256) __half g_wvt[2 * W_PLANE];
__device__ __align__(256) __half g_wzt[2 * W_PLANE];
__device__ __align__(256) __half g_qs [2 * QK_PLANE];
__device__ __align__(256) __half g_ks [2 * QK_PLANE];
__device__ __align__(256) __half g_vts[2 * QK_PLANE];   // [b,h,e,s]
__device__ __align__(256) __half g_zs [2 * Z_PLANE];    // [b,s,h*D]
__device__ __align__(256) __half g_ps [2 * ATTN_PLANE]; // split probs (x1024)

struct Off { int dv; long s1; int md; long s2; };

__device__ __forceinline__ uint32_t smem_u32(const void* p) {
    uint32_t a;
    asm("{ .reg .u64 t; cvta.to.shared.u64 t, %1; cvt.u32.u64 %0, t; }" : "=r"(a) : "l"(p));
    return a;
}
__device__ __forceinline__ void cpasync16(uint32_t dst, const void* src) {
    asm volatile("cp.async.cg.shared.global [%0], [%1], 16;" :: "r"(dst), "l"(src) : "memory");
}
#define CP_COMMIT() asm volatile("cp.async.commit_group;" ::: "memory")
#define CP_WAIT1()  asm volatile("cp.async.wait_group 1;" ::: "memory")
#define CP_WAIT0()  asm volatile("cp.async.wait_group 0;" ::: "memory")

#define LDSM4(r, a) \
    asm volatile("ldmatrix.sync.aligned.m8n8.x4.shared.b16 {%0,%1,%2,%3}, [%4];" \
        : "=r"((r)[0]), "=r"((r)[1]), "=r"((r)[2]), "=r"((r)[3]) : "r"(a))

#define MMAF(c, a, b0, b1) \
    asm volatile("mma.sync.aligned.m16n8k16.row.col.f32.f16.f16.f32 " \
        "{%0,%1,%2,%3},{%4,%5,%6,%7},{%8,%9},{%0,%1,%2,%3};" \
        : "+f"((c)[0]), "+f"((c)[1]), "+f"((c)[2]), "+f"((c)[3]) \
        : "r"((a)[0]), "r"((a)[1]), "r"((a)[2]), "r"((a)[3]), "r"(b0), "r"(b1))

#define MMAH(c, a, b0, b1) \
    asm volatile("mma.sync.aligned.m16n8k16.row.col.f16.f16.f16.f16 " \
        "{%0,%1},{%2,%3,%4,%5},{%6,%7},{%0,%1};" \
        : "+r"((c)[0]), "+r"((c)[1]) \
        : "r"((a)[0]), "r"((a)[1]), "r"((a)[2]), "r"((a)[3]), "r"(b0), "r"(b1))

__device__ __forceinline__ void split1(float x, __half& h, __half& l) {
    h = __float2half_rn(x);
    l = __float2half_rn(x - __half2float(h));
}

#define STAGE_B  16384
#define STAGE_SZ 32768
#define NSTAGE   3
#define SMEM_SZ  (NSTAGE * STAGE_SZ)
#define GTHREADS 512

// ---------------------------------------------------------------------------
// fp16 HMMA TN GEMM, split passes: p1 = Ah.Bh (f32acc, always);
// p2 = Ah.Bl (f16acc, if pmask&1); p3 = Al.Bh (f16acc, if pmask&2).
// Block 128x128, K-chunk 32, 16 warps, 3-stage cp.async.
// mode 0: fp32 out (+bias). mode 1: split-fp16 out. mode 2: split-fp16 transposed.
// ---------------------------------------------------------------------------
__global__ void __launch_bounds__(GTHREADS, 1)
gemm_mma(const __half* __restrict__ A, long aplane,
         const __half* __restrict__ B, long bplane,
         void* Cv, long cplane,
         int K, int lda, int ldb, int ldc,
         Off oa, Off ob, Off oc,
         float alpha, const float* __restrict__ bias, int mode, int pmask)
{
    extern __shared__ char smem[];
    const uint32_t sm = smem_u32(smem);
    const int tid = threadIdx.x, wid = tid >> 5, lane = tid & 31;
    const int z = blockIdx.z;

    const __half* Ahp = A + (long)(z / oa.dv) * oa.s1 + (long)(z % oa.md) * oa.s2;
    const __half* Bhp = B + (long)(z / ob.dv) * ob.s1 + (long)(z % ob.md) * ob.s2;
    const long coff = (long)(z / oc.dv) * oc.s1 + (long)(z % oc.md) * oc.s2;

    const long row0 = (long)blockIdx.y * 128;
    const long col0 = (long)blockIdx.x * 128;

    const int lrow = tid >> 2;
    const int c0   = (tid & 3) * 2;
    const int lpl  = c0 >> 2;
    const __half* Asrc = (lpl ? Ahp + aplane : Ahp) + (row0 + lrow) * lda + (c0 & 3) * 8;
    const __half* Bsrc = (lpl ? Bhp + bplane : Bhp) + (col0 + lrow) * ldb + (c0 & 3) * 8;
    uint32_t soff[2];
    #pragma unroll
    for (int j = 0; j < 2; ++j)
        soff[j] = lrow * 128 + (((c0 + j) ^ (lrow & 7)) << 4);

    const int wm = wid & 3, wn = wid >> 2;
    const int g = lane >> 3, r8 = lane & 7;
    const int a_roff = ((g & 1) << 3) + r8;
    const int a_kh   = g >> 1;
    const int b_roff = ((g >> 1) << 3) + r8;
    const int b_kh   = g & 1;

    uint32_t a_row[2], a_rx[2];
    #pragma unroll
    for (int mt = 0; mt < 2; ++mt) {
        const int row = wm * 32 + mt * 16 + a_roff;
        a_row[mt] = row * 128;
        a_rx[mt] = row & 7;
    }
    uint32_t b_row[2], b_rx[2];
    #pragma unroll
    for (int np = 0; np < 2; ++np) {
        const int row = wn * 32 + np * 16 + b_roff;
        b_row[np] = row * 128;
        b_rx[np] = row & 7;
    }

    float acc[2][4][4];
    uint32_t acch[2][4][2];
    #pragma unroll
    for (int i = 0; i < 2; ++i)
        #pragma unroll
        for (int j = 0; j < 4; ++j) {
            #pragma unroll
            for (int q = 0; q < 4; ++q) acc[i][j][q] = 0.0f;
            acch[i][j][0] = 0u; acch[i][j][1] = 0u;
        }

    const int nst = K / 32;

    #pragma unroll
    for (int p = 0; p < 2; ++p) {
        if (p < nst) {
            const uint32_t tb = sm + p * STAGE_SZ;
            const long k0 = (long)p * 32;
            #pragma unroll
            for (int j = 0; j < 2; ++j) {
                cpasync16(tb + soff[j], Asrc + k0 + j * 8);
                cpasync16(tb + STAGE_B + soff[j], Bsrc + k0 + j * 8);
            }
        }
        CP_COMMIT();
    }

    int stg = 0;
    for (int s = 0; s < nst; ++s) {
        if (s + 1 < nst) CP_WAIT1(); else CP_WAIT0();
        __syncthreads();

        const uint32_t tb = sm + stg * STAGE_SZ;
        const uint32_t tba = tb, tbb = tb + STAGE_B;

        #pragma unroll
        for (int ks = 0; ks < 2; ++ks) {
            const int ca = ks * 2 + a_kh;
            const int cb = ks * 2 + b_kh;

            // ---- pass 1: Ah x Bh (f32 acc)
            uint32_t Ahr[2][4], Bhr[2][4];
            #pragma unroll
            for (int mt = 0; mt < 2; ++mt)
                LDSM4(Ahr[mt], tba + a_row[mt] + ((ca ^ a_rx[mt]) << 4));
            #pragma unroll
            for (int np = 0; np < 2; ++np)
                LDSM4(Bhr[np], tbb + b_row[np] + ((cb ^ b_rx[np]) << 4));
            #pragma unroll
            for (int mt = 0; mt < 2; ++mt)
                #pragma unroll
                for (int nt = 0; nt < 4; ++nt) {
                    const int np = nt >> 1, s2 = (nt & 1) * 2;
                    MMAF(acc[mt][nt], Ahr[mt], Bhr[np][s2], Bhr[np][s2 + 1]);
                }

            // ---- pass 2: Ah x Bl (f16 acc)
            if (pmask & 1) {
                uint32_t Blr[2][4];
                #pragma unroll
                for (int np = 0; np < 2; ++np)
                    LDSM4(Blr[np], tbb + b_row[np] + (((cb + 4) ^ b_rx[np]) << 4));
                #pragma unroll
                for (int mt = 0; mt < 2; ++mt)
                    #pragma unroll
                    for (int nt = 0; nt < 4; ++nt) {
                        const int np = nt >> 1, s2 = (nt & 1) * 2;
                        MMAH(acch[mt][nt], Ahr[mt], Blr[np][s2], Blr[np][s2 + 1]);
                    }
            }

            // ---- pass 3: Al x Bh (f16 acc)
            if (pmask & 2) {
                uint32_t Alr[2][4];
                #pragma unroll
                for (int mt = 0; mt < 2; ++mt)
                    LDSM4(Alr[mt], tba + a_row[mt] + (((ca + 4) ^ a_rx[mt]) << 4));
                #pragma unroll
                for (int mt = 0; mt < 2; ++mt)
                    #pragma unroll
                    for (int nt = 0; nt < 4; ++nt) {
                        const int np = nt >> 1, s2 = (nt & 1) * 2;
                        MMAH(acch[mt][nt], Alr[mt], Bhr[np][s2], Bhr[np][s2 + 1]);
                    }
            }
        }

        if (s + 2 < nst) {
            int ps = stg + 2; if (ps >= NSTAGE) ps -= NSTAGE;
            const uint32_t pb = sm + ps * STAGE_SZ;
            const long k0 = (long)(s + 2) * 32;
            #pragma unroll
            for (int j = 0; j < 2; ++j) {
                cpasync16(pb + soff[j], Asrc + k0 + j * 8);
                cpasync16(pb + STAGE_B + soff[j], Bsrc + k0 + j * 8);
            }
        }
        CP_COMMIT();

        if (++stg == NSTAGE) stg = 0;
    }

    const int r_in = lane >> 2, c_in = (lane & 3) * 2;
    #pragma unroll
    for (int mt = 0; mt < 2; ++mt) {
        #pragma unroll
        for (int half = 0; half < 2; ++half) {
            const long row = row0 + wm * 32 + mt * 16 + half * 8 + r_in;
            #pragma unroll
            for (int nt = 0; nt < 4; ++nt) {
                const int colg = (int)col0 + wn * 32 + nt * 8 + c_in;
                float2 cf = __half22float2(*reinterpret_cast<__half2*>(&acch[mt][nt][half]));
                float v0 = (acc[mt][nt][half * 2 + 0] + cf.x) * alpha;
                float v1 = (acc[mt][nt][half * 2 + 1] + cf.y) * alpha;
                if (mode == 0) {
                    if (bias) { v0 += bias[colg]; v1 += bias[colg + 1]; }
                    *(float2*)((float*)Cv + coff + row * ldc + colg) = make_float2(v0, v1);
                } else if (mode == 1) {
                    __half h0, l0, h1, l1;
                    split1(v0, h0, l0); split1(v1, h1, l1);
                    __half2 hh; hh.x = h0; hh.y = h1;
                    __half2 ll; ll.x = l0; ll.y = l1;
                    __half* Ch = (__half*)Cv + coff + row * ldc + colg;
                    *(__half2*)Ch = hh;
                    *(__half2*)(Ch + cplane) = ll;
                } else {
                    __half h0, l0, h1, l1;
                    split1(v0, h0, l0); split1(v1, h1, l1);
                    __half* Ch = (__half*)Cv + coff;
                    const long o0 = (long)colg * ldc + row;
                    const long o1 = (long)(colg + 1) * ldc + row;
                    Ch[o0] = h0; Ch[o0 + cplane] = l0;
                    Ch[o1] = h1; Ch[o1 + cplane] = l1;
                }
            }
        }
    }
}

// ---------------------------------------------------------------------------
__global__ void __launch_bounds__(256) split_kernel(const float* __restrict__ in,
                                                    __half* __restrict__ hi, long plane,
                                                    float scale)
{
    const long idx = (long)blockIdx.x * 256 + threadIdx.x;
    float4 v = ((const float4*)in)[idx];
    __half h0, l0, h1, l1, h2, l2, h3, l3;
    split1(v.x * scale, h0, l0); split1(v.y * scale, h1, l1);
    split1(v.z * scale, h2, l2); split1(v.w * scale, h3, l3);
    __half2 a, b, c, d;
    a.x = h0; a.y = h1; b.x = h2; b.y = h3;
    c.x = l0; c.y = l1; d.x = l2; d.y = l3;
    ((__half2*)hi)[2 * idx]     = a;
    ((__half2*)hi)[2 * idx + 1] = b;
    ((__half2*)(hi + plane))[2 * idx]     = c;
    ((__half2*)(hi + plane))[2 * idx + 1] = d;
}

__global__ void __launch_bounds__(256) tsplit_kernel(const float* __restrict__ in,
                                                     __half* __restrict__ outh,
                                                     long plane, int R, int C, float scale)
{
    __shared__ float ts[32][33];
    const int tx = threadIdx.x, ty = threadIdx.y;
    const long zo = (long)blockIdx.z * R * C;
    const int r0 = blockIdx.y * 32, c0 = blockIdx.x * 32;
    #pragma unroll
    for (int i = 0; i < 4; ++i)
        ts[ty + 8 * i][tx] = in[zo + (long)(r0 + ty + 8 * i) * C + c0 + tx];
    __syncthreads();
    #pragma unroll
    for (int i = 0; i < 4; ++i) {
        __half h, l;
        split1(ts[tx][ty + 8 * i] * scale, h, l);
        const long o = zo + (long)(c0 + ty + 8 * i) * R + r0 + tx;
        outh[o] = h;
        outh[o + plane] = l;
    }
}

// fused softmax + head-average: one block per (b, row); loops all 8 heads.
// Writes split probs (x1024) to g_ps and attn_avg directly.
__global__ void __launch_bounds__(256) softmax_avg_kernel(float* __restrict__ avg_out)
{
    const int r = blockIdx.x & (Sq - 1);
    const int b = blockIdx.x >> 11;
    const int tid = threadIdx.x;
    __shared__ float sr[8];

    float avg[8];
    #pragma unroll
    for (int i = 0; i < 8; ++i) avg[i] = 0.0f;

    for (int h = 0; h < Hq; ++h) {
        const long rowo = (((long)b * Hq + h) * Sq + r) * Sq;
        const float* p = g_attn + rowo;

        float v[8];
        float mx = -1e30f;
        #pragma unroll
        for (int i = 0; i < 8; ++i) { v[i] = p[tid + i * 256]; mx = fmaxf(mx, v[i]); }
        #pragma unroll
        for (int o = 16; o > 0; o >>= 1) mx = fmaxf(mx, __shfl_xor_sync(~0u, mx, o));
        if ((tid & 31) == 0) sr[tid >> 5] = mx;
        __syncthreads();
        float m = sr[0];
        #pragma unroll
        for (int i = 1; i < 8; ++i) m = fmaxf(m, sr[i]);
        __syncthreads();
        float s = 0.f;
        #pragma unroll
        for (int i = 0; i < 8; ++i) { v[i] = __expf(v[i] - m); s += v[i]; }
        #pragma unroll
        for (int o = 16; o > 0; o >>= 1) s += __shfl_xor_sync(~0u, s, o);
        if ((tid & 31) == 0) sr[tid >> 5] = s;
        __syncthreads();
        float t = 0.f;
        #pragma unroll
        for (int i = 0; i < 8; ++i) t += sr[i];
        __syncthreads();

        const float inv = 1.0f / t;
        #pragma unroll
        for (int i = 0; i < 8; ++i) {
            const float pv = v[i] * inv;
            avg[i] += pv;
            __half hh, ll;
            split1(pv * 1024.0f, hh, ll);
            g_ps[rowo + tid + i * 256] = hh;
            g_ps[ATTN_PLANE + rowo + tid + i * 256] = ll;
        }
    }

    float* dst = avg_out + ((long)b * Sq + r) * Sq;
    #pragma unroll
    for (int i = 0; i < 8; ++i)
        dst[tid + i * 256] = avg[i] * 0.125f;
}

// ---------------------------------------------------------------------------
extern "C" void kernel_launch(void* const* d_in, const int* in_sizes, int n_in,
                              void* d_out, int out_size)
{
    (void)in_sizes; (void)n_in; (void)out_size;
    const float* Xq = (const float*)d_in[0];
    const float* Xk = (const float*)d_in[1];
    const float* Xv = (const float*)d_in[2];
    const float* Wq = (const float*)d_in[3];
    const float* Wk = (const float*)d_in[4];
    const float* Wv = (const float*)d_in[5];
    const float* Wz = (const float*)d_in[6];
    const float* bz = (const float*)d_in[7];
    float* out = (float*)d_out;
    float* attn_avg = out + (long)Bq * Sq * Dq;

    __half *pxq, *pxk, *pxv, *pwq, *pwk, *pwv, *pwz, *pqs, *pks, *pvt, *pzs, *pps;
    float* pattn;
    cudaGetSymbolAddress((void**)&pxq, g_xq);
    cudaGetSymbolAddress((void**)&pxk, g_xk);
    cudaGetSymbolAddress((void**)&pxv, g_xv);
    cudaGetSymbolAddress((void**)&pwq, g_wqt);
    cudaGetSymbolAddress((void**)&pwk, g_wkt);
    cudaGetSymbolAddress((void**)&pwv, g_wvt);
    cudaGetSymbolAddress((void**)&pwz, g_wzt);
    cudaGetSymbolAddress((void**)&pqs, g_qs);
    cudaGetSymbolAddress((void**)&pks, g_ks);
    cudaGetSymbolAddress((void**)&pvt, g_vts);
    cudaGetSymbolAddress((void**)&pzs, g_zs);
    cudaGetSymbolAddress((void**)&pps, g_ps);
    cudaGetSymbolAddress((void**)&pattn, g_attn);

    cudaFuncSetAttribute(gemm_mma, cudaFuncAttributeMaxDynamicSharedMemorySize, SMEM_SZ);

    const float inv4 = (float)(1.0 / pow((double)Dq, 0.25));

    // 1) split inputs; transpose+split weights (Wq/k/v x16, Wz x64)
    {
        int nb = (int)(X_PLANE / 1024);
        split_kernel<<<nb, 256>>>(Xq, pxq, X_PLANE, 1.0f);
        split_kernel<<<nb, 256>>>(Xk, pxk, X_PLANE, 1.0f);
        split_kernel<<<nb, 256>>>(Xv, pxv, X_PLANE, 1.0f);
        dim3 tb(32, 8);
        tsplit_kernel<<<dim3(16, 16, 8), tb>>>(Wq, pwq, W_PLANE, Dq, Dq, 16.0f);
        tsplit_kernel<<<dim3(16, 16, 8), tb>>>(Wk, pwk, W_PLANE, Dq, Dq, 16.0f);
        tsplit_kernel<<<dim3(16, 16, 8), tb>>>(Wv, pwv, W_PLANE, Dq, Dq, 16.0f);
        tsplit_kernel<<<dim3(16, 128, 1), tb>>>(Wz, pwz, W_PLANE, Hq * Dq, Dq, 64.0f);
    }

    // 2) projections (TN), full 3-pass. q_s/k_s = 4x true, v_s = 4x v.
    {
        dim3 grid(Dq / 128, Sq / 128, Bq * Hq);
        Off oa = { Hq, SDc, 1, 0 };
        Off ob = { 1, 0, Hq, DDc };
        Off oc = { 1, SDc, 1, 0 };
        gemm_mma<<<grid, GTHREADS, SMEM_SZ>>>(pxq, X_PLANE, pwq, W_PLANE, pqs, QK_PLANE,
                                              Dq, Dq, Dq, Dq, oa, ob, oc, inv4 * 0.25f, nullptr, 1, 3);
        gemm_mma<<<grid, GTHREADS, SMEM_SZ>>>(pxk, X_PLANE, pwk, W_PLANE, pks, QK_PLANE,
                                              Dq, Dq, Dq, Dq, oa, ob, oc, inv4 * 0.25f, nullptr, 1, 3);
        gemm_mma<<<grid, GTHREADS, SMEM_SZ>>>(pxv, X_PLANE, pwv, W_PLANE, pvt, QK_PLANE,
                                              Dq, Dq, Dq, Sq, oa, ob, oc, 0.25f, nullptr, 2, 3);
    }

    // 3) scores (fp32) = q_s.k_s / 16, full 3-pass
    {
        dim3 grid(Sq / 128, Sq / 128, Bq * Hq);
        Off oa = { 1, SDc, 1, 0 };
        Off ob = { 1, SDc, 1, 0 };
        Off oc = { 1, SSc, 1, 0 };
        gemm_mma<<<grid, GTHREADS, SMEM_SZ>>>(pqs, QK_PLANE, pks, QK_PLANE, pattn, 0,
                                              Dq, Dq, Dq, Sq, oa, ob, oc, 1.0f / 16.0f, nullptr, 0, 3);
    }

    // 4) fused softmax + head-average
    softmax_avg_kernel<<<Bq * Sq, 256>>>(attn_avg);

    // 5) z_s = 32*z = (p_s . v_s)/128; drop V_lo correction (pmask=2: keep P_lo.V_hi)
    {
        dim3 grid(Dq / 128, Sq / 128, Bq * Hq);
        Off oa = { 1, SSc, 1, 0 };
        Off ob = { 1, SDc, 1, 0 };
        Off oc = { Hq, (long)Sq * Hq * Dq, Hq, (long)Dq };
        gemm_mma<<<grid, GTHREADS, SMEM_SZ>>>(pps, ATTN_PLANE, pvt, QK_PLANE, pzs, Z_PLANE,
                                              Sq, Sq, Sq, Hq * Dq, oa, ob, oc, 1.0f / 128.0f, nullptr, 1, 2);
    }

    // 6) out = (z_s . wz_s)/2048 + bz; drop z_lo correction (pmask=1: keep Wz_lo)
    {
        dim3 grid(Dq / 128, (Bq * Sq) / 128, 1);
        Off oz = { 1, 0, 1, 0 };
        gemm_mma<<<grid, GTHREADS, SMEM_SZ>>>(pzs, Z_PLANE, pwz, W_PLANE, out, 0,
                                              Hq * Dq, Hq * Dq, Hq * Dq, Dq,
                                              oz, oz, oz, 1.0f / 2048.0f, bz, 0, 1);
    }
}

// round 10
// speedup vs baseline: 1.6586x; 1.1104x over previous
#include <cuda_runtime.h>
#include <cuda_fp16.h>
#include <math.h>
#include <stdint.h>

#define Bq 2
#define Sq 2048
#define Dq 512
#define Hq 8

#define SDc  ((long)Sq * Dq)
#define SSc  ((long)Sq * Sq)
#define DDc  ((long)Dq * Dq)

#define X_PLANE    ((long)Bq * Sq * Dq)
#define W_PLANE    ((long)Hq * Dq * Dq)
#define QK_PLANE   ((long)Bq * Hq * Sq * Dq)
#define ATTN_PLANE ((long)Bq * Hq * Sq * Sq)
#define Z_PLANE    QK_PLANE

__device__ __align__(256) float g_attn[ATTN_PLANE];
__device__ __align__(256) __half g_xq [2 * X_PLANE];
__device__ __align__(256) __half g_xk [2 * X_PLANE];
__device__ __align__(256) __half g_xv [2 * X_PLANE];
__device__ __align__(256) __half g_wqt[2 * W_PLANE];
__device__ __align__(256) __half g_wkt[2 * W_PLANE];
__device__ __align__(256) __half g_wvt[2 * W_PLANE];
__device__ __align__(256) __half g_wzt[2 * W_PLANE];
__device__ __align__(256) __half g_qs [2 * QK_PLANE];
__device__ __align__(256) __half g_ks [2 * QK_PLANE];
__device__ __align__(256) __half g_vts[2 * QK_PLANE];   // [b,h,e,s]
__device__ __align__(256) __half g_zs [2 * Z_PLANE];    // [b,s,h*D]
__device__ __align__(256) __half g_ps [2 * ATTN_PLANE]; // split probs (x1024)

struct Off { int dv; long s1; int md; long s2; };

__device__ __forceinline__ uint32_t smem_u32(const void* p) {
    uint32_t a;
    asm("{ .reg .u64 t; cvta.to.shared.u64 t, %1; cvt.u32.u64 %0, t; }" : "=r"(a) : "l"(p));
    return a;
}
__device__ __forceinline__ void cpasync16(uint32_t dst, const void* src) {
    asm volatile("cp.async.cg.shared.global [%0], [%1], 16;" :: "r"(dst), "l"(src) : "memory");
}
#define CP_COMMIT() asm volatile("cp.async.commit_group;" ::: "memory")
#define CP_WAIT1()  asm volatile("cp.async.wait_group 1;" ::: "memory")
#define CP_WAIT0()  asm volatile("cp.async.wait_group 0;" ::: "memory")

#define LDSM4(r, a) \
    asm volatile("ldmatrix.sync.aligned.m8n8.x4.shared.b16 {%0,%1,%2,%3}, [%4];" \
        : "=r"((r)[0]), "=r"((r)[1]), "=r"((r)[2]), "=r"((r)[3]) : "r"(a))

#define MMAF(c, a, b0, b1) \
    asm volatile("mma.sync.aligned.m16n8k16.row.col.f32.f16.f16.f32 " \
        "{%0,%1,%2,%3},{%4,%5,%6,%7},{%8,%9},{%0,%1,%2,%3};" \
        : "+f"((c)[0]), "+f"((c)[1]), "+f"((c)[2]), "+f"((c)[3]) \
        : "r"((a)[0]), "r"((a)[1]), "r"((a)[2]), "r"((a)[3]), "r"(b0), "r"(b1))

#define MMAH(c, a, b0, b1) \
    asm volatile("mma.sync.aligned.m16n8k16.row.col.f16.f16.f16.f16 " \
        "{%0,%1},{%2,%3,%4,%5},{%6,%7},{%0,%1};" \
        : "+r"((c)[0]), "+r"((c)[1]) \
        : "r"((a)[0]), "r"((a)[1]), "r"((a)[2]), "r"((a)[3]), "r"(b0), "r"(b1))

__device__ __forceinline__ void split1(float x, __half& h, __half& l) {
    h = __float2half_rn(x);
    l = __float2half_rn(x - __half2float(h));
}

#define STAGE_B  16384
#define STAGE_SZ 32768
#define NSTAGE   3
#define SMEM_SZ  (NSTAGE * STAGE_SZ)
#define GTHREADS 512

// ---------------------------------------------------------------------------
// fp16 HMMA TN GEMM, split passes (compile-time PMASK):
// p1 = Ah.Bh (f32acc, always); p2 = Ah.Bl (f16acc, PMASK&1); p3 = Al.Bh (f16acc, PMASK&2).
// Block 128x128, K-chunk 32, 16 warps, 3-stage cp.async.
// mode 0: fp32 out (+bias). mode 1: split-fp16 out. mode 2: split-fp16 transposed.
// ---------------------------------------------------------------------------
template <int PMASK>
__global__ void __launch_bounds__(GTHREADS, 1)
gemm_mma(const __half* __restrict__ A, long aplane,
         const __half* __restrict__ B, long bplane,
         void* Cv, long cplane,
         int K, int lda, int ldb, int ldc,
         Off oa, Off ob, Off oc,
         float alpha, const float* __restrict__ bias, int mode)
{
    extern __shared__ char smem[];
    const uint32_t sm = smem_u32(smem);
    const int tid = threadIdx.x, wid = tid >> 5, lane = tid & 31;
    const int z = blockIdx.z;

    const __half* Ahp = A + (long)(z / oa.dv) * oa.s1 + (long)(z % oa.md) * oa.s2;
    const __half* Bhp = B + (long)(z / ob.dv) * ob.s1 + (long)(z % ob.md) * ob.s2;
    const long coff = (long)(z / oc.dv) * oc.s1 + (long)(z % oc.md) * oc.s2;

    const long row0 = (long)blockIdx.y * 128;
    const long col0 = (long)blockIdx.x * 128;

    const int lrow = tid >> 2;
    const int c0   = (tid & 3) * 2;
    const int lpl  = c0 >> 2;
    const __half* Asrc = (lpl ? Ahp + aplane : Ahp) + (row0 + lrow) * lda + (c0 & 3) * 8;
    const __half* Bsrc = (lpl ? Bhp + bplane : Bhp) + (col0 + lrow) * ldb + (c0 & 3) * 8;
    uint32_t soff[2];
    #pragma unroll
    for (int j = 0; j < 2; ++j)
        soff[j] = lrow * 128 + (((c0 + j) ^ (lrow & 7)) << 4);

    const int wm = wid & 3, wn = wid >> 2;
    const int g = lane >> 3, r8 = lane & 7;
    const int a_roff = ((g & 1) << 3) + r8;
    const int a_kh   = g >> 1;
    const int b_roff = ((g >> 1) << 3) + r8;
    const int b_kh   = g & 1;

    uint32_t a_row[2], a_rx[2];
    #pragma unroll
    for (int mt = 0; mt < 2; ++mt) {
        const int row = wm * 32 + mt * 16 + a_roff;
        a_row[mt] = row * 128;
        a_rx[mt] = row & 7;
    }
    uint32_t b_row[2], b_rx[2];
    #pragma unroll
    for (int np = 0; np < 2; ++np) {
        const int row = wn * 32 + np * 16 + b_roff;
        b_row[np] = row * 128;
        b_rx[np] = row & 7;
    }

    float acc[2][4][4];
    uint32_t acch[2][4][2];
    #pragma unroll
    for (int i = 0; i < 2; ++i)
        #pragma unroll
        for (int j = 0; j < 4; ++j) {
            #pragma unroll
            for (int q = 0; q < 4; ++q) acc[i][j][q] = 0.0f;
            acch[i][j][0] = 0u; acch[i][j][1] = 0u;
        }

    const int nst = K / 32;

    #pragma unroll
    for (int p = 0; p < 2; ++p) {
        if (p < nst) {
            const uint32_t tb = sm + p * STAGE_SZ;
            const long k0 = (long)p * 32;
            #pragma unroll
            for (int j = 0; j < 2; ++j) {
                cpasync16(tb + soff[j], Asrc + k0 + j * 8);
                cpasync16(tb + STAGE_B + soff[j], Bsrc + k0 + j * 8);
            }
        }
        CP_COMMIT();
    }

    int stg = 0;
    for (int s = 0; s < nst; ++s) {
        if (s + 1 < nst) CP_WAIT1(); else CP_WAIT0();
        __syncthreads();

        const uint32_t tb = sm + stg * STAGE_SZ;
        const uint32_t tba = tb, tbb = tb + STAGE_B;

        #pragma unroll
        for (int ks = 0; ks < 2; ++ks) {
            const int ca = ks * 2 + a_kh;
            const int cb = ks * 2 + b_kh;

            // ---- pass 1: Ah x Bh (f32 acc)
            uint32_t Ahr[2][4], Bhr[2][4];
            #pragma unroll
            for (int mt = 0; mt < 2; ++mt)
                LDSM4(Ahr[mt], tba + a_row[mt] + ((ca ^ a_rx[mt]) << 4));
            #pragma unroll
            for (int np = 0; np < 2; ++np)
                LDSM4(Bhr[np], tbb + b_row[np] + ((cb ^ b_rx[np]) << 4));
            #pragma unroll
            for (int mt = 0; mt < 2; ++mt)
                #pragma unroll
                for (int nt = 0; nt < 4; ++nt) {
                    const int np = nt >> 1, s2 = (nt & 1) * 2;
                    MMAF(acc[mt][nt], Ahr[mt], Bhr[np][s2], Bhr[np][s2 + 1]);
                }

            // ---- pass 2: Ah x Bl (f16 acc)
            if (PMASK & 1) {
                uint32_t Blr[2][4];
                #pragma unroll
                for (int np = 0; np < 2; ++np)
                    LDSM4(Blr[np], tbb + b_row[np] + (((cb + 4) ^ b_rx[np]) << 4));
                #pragma unroll
                for (int mt = 0; mt < 2; ++mt)
                    #pragma unroll
                    for (int nt = 0; nt < 4; ++nt) {
                        const int np = nt >> 1, s2 = (nt & 1) * 2;
                        MMAH(acch[mt][nt], Ahr[mt], Blr[np][s2], Blr[np][s2 + 1]);
                    }
            }

            // ---- pass 3: Al x Bh (f16 acc)
            if (PMASK & 2) {
                uint32_t Alr[2][4];
                #pragma unroll
                for (int mt = 0; mt < 2; ++mt)
                    LDSM4(Alr[mt], tba + a_row[mt] + (((ca + 4) ^ a_rx[mt]) << 4));
                #pragma unroll
                for (int mt = 0; mt < 2; ++mt)
                    #pragma unroll
                    for (int nt = 0; nt < 4; ++nt) {
                        const int np = nt >> 1, s2 = (nt & 1) * 2;
                        MMAH(acch[mt][nt], Alr[mt], Bhr[np][s2], Bhr[np][s2 + 1]);
                    }
            }
        }

        if (s + 2 < nst) {
            int ps = stg + 2; if (ps >= NSTAGE) ps -= NSTAGE;
            const uint32_t pb = sm + ps * STAGE_SZ;
            const long k0 = (long)(s + 2) * 32;
            #pragma unroll
            for (int j = 0; j < 2; ++j) {
                cpasync16(pb + soff[j], Asrc + k0 + j * 8);
                cpasync16(pb + STAGE_B + soff[j], Bsrc + k0 + j * 8);
            }
        }
        CP_COMMIT();

        if (++stg == NSTAGE) stg = 0;
    }

    const int r_in = lane >> 2, c_in = (lane & 3) * 2;
    #pragma unroll
    for (int mt = 0; mt < 2; ++mt) {
        #pragma unroll
        for (int half = 0; half < 2; ++half) {
            const long row = row0 + wm * 32 + mt * 16 + half * 8 + r_in;
            #pragma unroll
            for (int nt = 0; nt < 4; ++nt) {
                const int colg = (int)col0 + wn * 32 + nt * 8 + c_in;
                float2 cf = __half22float2(*reinterpret_cast<__half2*>(&acch[mt][nt][half]));
                float v0 = (acc[mt][nt][half * 2 + 0] + cf.x) * alpha;
                float v1 = (acc[mt][nt][half * 2 + 1] + cf.y) * alpha;
                if (mode == 0) {
                    if (bias) { v0 += bias[colg]; v1 += bias[colg + 1]; }
                    *(float2*)((float*)Cv + coff + row * ldc + colg) = make_float2(v0, v1);
                } else if (mode == 1) {
                    __half h0, l0, h1, l1;
                    split1(v0, h0, l0); split1(v1, h1, l1);
                    __half2 hh; hh.x = h0; hh.y = h1;
                    __half2 ll; ll.x = l0; ll.y = l1;
                    __half* Ch = (__half*)Cv + coff + row * ldc + colg;
                    *(__half2*)Ch = hh;
                    *(__half2*)(Ch + cplane) = ll;
                } else {
                    __half h0, l0, h1, l1;
                    split1(v0, h0, l0); split1(v1, h1, l1);
                    __half* Ch = (__half*)Cv + coff;
                    const long o0 = (long)colg * ldc + row;
                    const long o1 = (long)(colg + 1) * ldc + row;
                    Ch[o0] = h0; Ch[o0 + cplane] = l0;
                    Ch[o1] = h1; Ch[o1 + cplane] = l1;
                }
            }
        }
    }
}

// ---------------------------------------------------------------------------
__global__ void __launch_bounds__(256) split_kernel(const float* __restrict__ in,
                                                    __half* __restrict__ hi, long plane,
                                                    float scale)
{
    const long idx = (long)blockIdx.x * 256 + threadIdx.x;
    float4 v = ((const float4*)in)[idx];
    __half h0, l0, h1, l1, h2, l2, h3, l3;
    split1(v.x * scale, h0, l0); split1(v.y * scale, h1, l1);
    split1(v.z * scale, h2, l2); split1(v.w * scale, h3, l3);
    __half2 a, b, c, d;
    a.x = h0; a.y = h1; b.x = h2; b.y = h3;
    c.x = l0; c.y = l1; d.x = l2; d.y = l3;
    ((__half2*)hi)[2 * idx]     = a;
    ((__half2*)hi)[2 * idx + 1] = b;
    ((__half2*)(hi + plane))[2 * idx]     = c;
    ((__half2*)(hi + plane))[2 * idx + 1] = d;
}

__global__ void __launch_bounds__(256) tsplit_kernel(const float* __restrict__ in,
                                                     __half* __restrict__ outh,
                                                     long plane, int R, int C, float scale)
{
    __shared__ float ts[32][33];
    const int tx = threadIdx.x, ty = threadIdx.y;
    const long zo = (long)blockIdx.z * R * C;
    const int r0 = blockIdx.y * 32, c0 = blockIdx.x * 32;
    #pragma unroll
    for (int i = 0; i < 4; ++i)
        ts[ty + 8 * i][tx] = in[zo + (long)(r0 + ty + 8 * i) * C + c0 + tx];
    __syncthreads();
    #pragma unroll
    for (int i = 0; i < 4; ++i) {
        __half h, l;
        split1(ts[tx][ty + 8 * i] * scale, h, l);
        const long o = zo + (long)(c0 + ty + 8 * i) * R + r0 + tx;
        outh[o] = h;
        outh[o + plane] = l;
    }
}

// fused softmax + head-average: one block per (b, row); loops all 8 heads.
__global__ void __launch_bounds__(256) softmax_avg_kernel(float* __restrict__ avg_out)
{
    const int r = blockIdx.x & (Sq - 1);
    const int b = blockIdx.x >> 11;
    const int tid = threadIdx.x;
    __shared__ float sr[8];

    float avg[8];
    #pragma unroll
    for (int i = 0; i < 8; ++i) avg[i] = 0.0f;

    for (int h = 0; h < Hq; ++h) {
        const long rowo = (((long)b * Hq + h) * Sq + r) * Sq;
        const float* p = g_attn + rowo;

        float v[8];
        float mx = -1e30f;
        #pragma unroll
        for (int i = 0; i < 8; ++i) { v[i] = p[tid + i * 256]; mx = fmaxf(mx, v[i]); }
        #pragma unroll
        for (int o = 16; o > 0; o >>= 1) mx = fmaxf(mx, __shfl_xor_sync(~0u, mx, o));
        if ((tid & 31) == 0) sr[tid >> 5] = mx;
        __syncthreads();
        float m = sr[0];
        #pragma unroll
        for (int i = 1; i < 8; ++i) m = fmaxf(m, sr[i]);
        __syncthreads();
        float s = 0.f;
        #pragma unroll
        for (int i = 0; i < 8; ++i) { v[i] = __expf(v[i] - m); s += v[i]; }
        #pragma unroll
        for (int o = 16; o > 0; o >>= 1) s += __shfl_xor_sync(~0u, s, o);
        if ((tid & 31) == 0) sr[tid >> 5] = s;
        __syncthreads();
        float t = 0.f;
        #pragma unroll
        for (int i = 0; i < 8; ++i) t += sr[i];
        __syncthreads();

        const float inv = 1.0f / t;
        #pragma unroll
        for (int i = 0; i < 8; ++i) {
            const float pv = v[i] * inv;
            avg[i] += pv;
            __half hh, ll;
            split1(pv * 1024.0f, hh, ll);
            g_ps[rowo + tid + i * 256] = hh;
            g_ps[ATTN_PLANE + rowo + tid + i * 256] = ll;
        }
    }

    float* dst = avg_out + ((long)b * Sq + r) * Sq;
    #pragma unroll
    for (int i = 0; i < 8; ++i)
        dst[tid + i * 256] = avg[i] * 0.125f;
}

// ---------------------------------------------------------------------------
extern "C" void kernel_launch(void* const* d_in, const int* in_sizes, int n_in,
                              void* d_out, int out_size)
{
    (void)in_sizes; (void)n_in; (void)out_size;
    const float* Xq = (const float*)d_in[0];
    const float* Xk = (const float*)d_in[1];
    const float* Xv = (const float*)d_in[2];
    const float* Wq = (const float*)d_in[3];
    const float* Wk = (const float*)d_in[4];
    const float* Wv = (const float*)d_in[5];
    const float* Wz = (const float*)d_in[6];
    const float* bz = (const float*)d_in[7];
    float* out = (float*)d_out;
    float* attn_avg = out + (long)Bq * Sq * Dq;

    __half *pxq, *pxk, *pxv, *pwq, *pwk, *pwv, *pwz, *pqs, *pks, *pvt, *pzs, *pps;
    float* pattn;
    cudaGetSymbolAddress((void**)&pxq, g_xq);
    cudaGetSymbolAddress((void**)&pxk, g_xk);
    cudaGetSymbolAddress((void**)&pxv, g_xv);
    cudaGetSymbolAddress((void**)&pwq, g_wqt);
    cudaGetSymbolAddress((void**)&pwk, g_wkt);
    cudaGetSymbolAddress((void**)&pwv, g_wvt);
    cudaGetSymbolAddress((void**)&pwz, g_wzt);
    cudaGetSymbolAddress((void**)&pqs, g_qs);
    cudaGetSymbolAddress((void**)&pks, g_ks);
    cudaGetSymbolAddress((void**)&pvt, g_vts);
    cudaGetSymbolAddress((void**)&pzs, g_zs);
    cudaGetSymbolAddress((void**)&pps, g_ps);
    cudaGetSymbolAddress((void**)&pattn, g_attn);

    cudaFuncSetAttribute(gemm_mma<3>, cudaFuncAttributeMaxDynamicSharedMemorySize, SMEM_SZ);
    cudaFuncSetAttribute(gemm_mma<2>, cudaFuncAttributeMaxDynamicSharedMemorySize, SMEM_SZ);
    cudaFuncSetAttribute(gemm_mma<1>, cudaFuncAttributeMaxDynamicSharedMemorySize, SMEM_SZ);

    const float inv4 = (float)(1.0 / pow((double)Dq, 0.25));

    // 1) split inputs; transpose+split weights (Wq/k/v x16, Wz x64)
    {
        int nb = (int)(X_PLANE / 1024);
        split_kernel<<<nb, 256>>>(Xq, pxq, X_PLANE, 1.0f);
        split_kernel<<<nb, 256>>>(Xk, pxk, X_PLANE, 1.0f);
        split_kernel<<<nb, 256>>>(Xv, pxv, X_PLANE, 1.0f);
        dim3 tb(32, 8);
        tsplit_kernel<<<dim3(16, 16, 8), tb>>>(Wq, pwq, W_PLANE, Dq, Dq, 16.0f);
        tsplit_kernel<<<dim3(16, 16, 8), tb>>>(Wk, pwk, W_PLANE, Dq, Dq, 16.0f);
        tsplit_kernel<<<dim3(16, 16, 8), tb>>>(Wv, pwv, W_PLANE, Dq, Dq, 16.0f);
        tsplit_kernel<<<dim3(16, 128, 1), tb>>>(Wz, pwz, W_PLANE, Hq * Dq, Dq, 64.0f);
    }

    // 2) projections (TN), full 3-pass. q_s/k_s = 4x true, v_s = 4x v.
    {
        dim3 grid(Dq / 128, Sq / 128, Bq * Hq);
        Off oa = { Hq, SDc, 1, 0 };
        Off ob = { 1, 0, Hq, DDc };
        Off oc = { 1, SDc, 1, 0 };
        gemm_mma<3><<<grid, GTHREADS, SMEM_SZ>>>(pxq, X_PLANE, pwq, W_PLANE, pqs, QK_PLANE,
                                                 Dq, Dq, Dq, Dq, oa, ob, oc, inv4 * 0.25f, nullptr, 1);
        gemm_mma<3><<<grid, GTHREADS, SMEM_SZ>>>(pxk, X_PLANE, pwk, W_PLANE, pks, QK_PLANE,
                                                 Dq, Dq, Dq, Dq, oa, ob, oc, inv4 * 0.25f, nullptr, 1);
        gemm_mma<3><<<grid, GTHREADS, SMEM_SZ>>>(pxv, X_PLANE, pwv, W_PLANE, pvt, QK_PLANE,
                                                 Dq, Dq, Dq, Sq, oa, ob, oc, 0.25f, nullptr, 2);
    }

    // 3) scores (fp32) = q_s.k_s / 16, full 3-pass
    {
        dim3 grid(Sq / 128, Sq / 128, Bq * Hq);
        Off oa = { 1, SDc, 1, 0 };
        Off ob = { 1, SDc, 1, 0 };
        Off oc = { 1, SSc, 1, 0 };
        gemm_mma<3><<<grid, GTHREADS, SMEM_SZ>>>(pqs, QK_PLANE, pks, QK_PLANE, pattn, 0,
                                                 Dq, Dq, Dq, Sq, oa, ob, oc, 1.0f / 16.0f, nullptr, 0);
    }

    // 4) fused softmax + head-average
    softmax_avg_kernel<<<Bq * Sq, 256>>>(attn_avg);

    // 5) z_s = 32*z = (p_s . v_s)/128; drop V_lo (keep P_lo.V_hi => PMASK=2)
    {
        dim3 grid(Dq / 128, Sq / 128, Bq * Hq);
        Off oa = { 1, SSc, 1, 0 };
        Off ob = { 1, SDc, 1, 0 };
        Off oc = { Hq, (long)Sq * Hq * Dq, Hq, (long)Dq };
        gemm_mma<2><<<grid, GTHREADS, SMEM_SZ>>>(pps, ATTN_PLANE, pvt, QK_PLANE, pzs, Z_PLANE,
                                                 Sq, Sq, Sq, Hq * Dq, oa, ob, oc, 1.0f / 128.0f, nullptr, 1);
    }

    // 6) out = (z_s . wz_s)/2048 + bz; drop z_lo (keep Zh.Wz_lo => PMASK=1)
    {
        dim3 grid(Dq / 128, (Bq * Sq) / 128, 1);
        Off oz = { 1, 0, 1, 0 };
        gemm_mma<1><<<grid, GTHREADS, SMEM_SZ>>>(pzs, Z_PLANE, pwz, W_PLANE, out, 0,
                                                 Hq * Dq, Hq * Dq, Hq * Dq, Dq,
                                                 oz, oz, oz, 1.0f / 2048.0f, bz, 0);
    }
}

// round 11
// speedup vs baseline: 2.3258x; 1.4022x over previous
#include <cuda_runtime.h>
#include <cuda_fp16.h>
#include <math.h>
#include <stdint.h>

#define Bq 2
#define Sq 2048
#define Dq 512
#define Hq 8

#define SDc  ((long)Sq * Dq)
#define SSc  ((long)Sq * Sq)
#define DDc  ((long)Dq * Dq)

#define X_PLANE    ((long)Bq * Sq * Dq)
#define W_PLANE    ((long)Hq * Dq * Dq)
#define QK_PLANE   ((long)Bq * Hq * Sq * Dq)
#define ATTN_PLANE ((long)Bq * Hq * Sq * Sq)
#define Z_PLANE    QK_PLANE

__device__ __align__(256) float g_attn[ATTN_PLANE];
__device__ __align__(256) __half g_xq [2 * X_PLANE];
__device__ __align__(256) __half g_xk [2 * X_PLANE];
__device__ __align__(256) __half g_xv [2 * X_PLANE];
__device__ __align__(256) __half g_wqt[2 * W_PLANE];
__device__ __align__(256) __half g_wkt[2 * W_PLANE];
__device__ __align__(256) __half g_wvt[2 * W_PLANE];
__device__ __align__(256) __half g_wzt[2 * W_PLANE];
__device__ __align__(256) __half g_qs [2 * QK_PLANE];
__device__ __align__(256) __half g_ks [2 * QK_PLANE];
__device__ __align__(256) __half g_vts[2 * QK_PLANE];   // [b,h,e,s]
__device__ __align__(256) __half g_zs [2 * Z_PLANE];    // [b,s,h*D]
__device__ __align__(256) __half g_ps [2 * ATTN_PLANE]; // split probs (x1024)

struct Off { int dv; long s1; int md; long s2; };

__device__ __forceinline__ uint32_t smem_u32(const void* p) {
    uint32_t a;
    asm("{ .reg .u64 t; cvta.to.shared.u64 t, %1; cvt.u32.u64 %0, t; }" : "=r"(a) : "l"(p));
    return a;
}
__device__ __forceinline__ void cpasync16(uint32_t dst, const void* src) {
    asm volatile("cp.async.cg.shared.global [%0], [%1], 16;" :: "r"(dst), "l"(src) : "memory");
}
#define CP_COMMIT() asm volatile("cp.async.commit_group;" ::: "memory")
#define CP_WAIT1()  asm volatile("cp.async.wait_group 1;" ::: "memory")
#define CP_WAIT0()  asm volatile("cp.async.wait_group 0;" ::: "memory")

#define LDSM4(r, a) \
    asm volatile("ldmatrix.sync.aligned.m8n8.x4.shared.b16 {%0,%1,%2,%3}, [%4];" \
        : "=r"((r)[0]), "=r"((r)[1]), "=r"((r)[2]), "=r"((r)[3]) : "r"(a))

#define MMAF(c, a, b0, b1) \
    asm volatile("mma.sync.aligned.m16n8k16.row.col.f32.f16.f16.f32 " \
        "{%0,%1,%2,%3},{%4,%5,%6,%7},{%8,%9},{%0,%1,%2,%3};" \
        : "+f"((c)[0]), "+f"((c)[1]), "+f"((c)[2]), "+f"((c)[3]) \
        : "r"((a)[0]), "r"((a)[1]), "r"((a)[2]), "r"((a)[3]), "r"(b0), "r"(b1))

#define MMAH(c, a, b0, b1) \
    asm volatile("mma.sync.aligned.m16n8k16.row.col.f16.f16.f16.f16 " \
        "{%0,%1},{%2,%3,%4,%5},{%6,%7},{%0,%1};" \
        : "+r"((c)[0]), "+r"((c)[1]) \
        : "r"((a)[0]), "r"((a)[1]), "r"((a)[2]), "r"((a)[3]), "r"(b0), "r"(b1))

__device__ __forceinline__ void split1(float x, __half& h, __half& l) {
    h = __float2half_rn(x);
    l = __float2half_rn(x - __half2float(h));
}

#define STAGE_B  16384
#define STAGE_SZ 32768
#define NSTAGE   3
#define SMEM_SZ  (NSTAGE * STAGE_SZ)
#define GTHREADS 512

// ---------------------------------------------------------------------------
// fp16 HMMA TN GEMM, split passes (compile-time PMASK):
// p1 = Ah.Bh (f32acc, always); p2 = Ah.Bl (f16acc, PMASK&1); p3 = Al.Bh (f16acc, PMASK&2).
// Loader skips lo-plane cp.async for planes no pass reads.
// Block 128x128, K-chunk 32, 16 warps, 3-stage cp.async.
// mode 0: fp32 out (+bias). mode 1: split-fp16 out. mode 2: split-fp16 transposed.
// writeLo: store the lo plane (modes 1/2) only if a later GEMM reads it.
// ---------------------------------------------------------------------------
template <int PMASK>
__global__ void __launch_bounds__(GTHREADS, 1)
gemm_mma(const __half* __restrict__ A, long aplane,
         const __half* __restrict__ B, long bplane,
         void* Cv, long cplane,
         int K, int lda, int ldb, int ldc,
         Off oa, Off ob, Off oc,
         float alpha, const float* __restrict__ bias, int mode, int writeLo)
{
    constexpr bool needBlo = (PMASK & 1) != 0;
    constexpr bool needAlo = (PMASK & 2) != 0;

    extern __shared__ char smem[];
    const uint32_t sm = smem_u32(smem);
    const int tid = threadIdx.x, wid = tid >> 5, lane = tid & 31;
    const int z = blockIdx.z;

    const __half* Ahp = A + (long)(z / oa.dv) * oa.s1 + (long)(z % oa.md) * oa.s2;
    const __half* Bhp = B + (long)(z / ob.dv) * ob.s1 + (long)(z % ob.md) * ob.s2;
    const long coff = (long)(z / oc.dv) * oc.s1 + (long)(z % oc.md) * oc.s2;

    const long row0 = (long)blockIdx.y * 128;
    const long col0 = (long)blockIdx.x * 128;

    const int lrow = tid >> 2;
    const int c0   = (tid & 3) * 2;
    const int lpl  = c0 >> 2;            // 0 = hi chunks (0-3), 1 = lo chunks (4-7)
    const __half* Asrc = (lpl ? Ahp + aplane : Ahp) + (row0 + lrow) * lda + (c0 & 3) * 8;
    const __half* Bsrc = (lpl ? Bhp + bplane : Bhp) + (col0 + lrow) * ldb + (c0 & 3) * 8;
    const bool doA = (lpl == 0) || needAlo;
    const bool doB = (lpl == 0) || needBlo;
    uint32_t soff[2];
    #pragma unroll
    for (int j = 0; j < 2; ++j)
        soff[j] = lrow * 128 + (((c0 + j) ^ (lrow & 7)) << 4);

    const int wm = wid & 3, wn = wid >> 2;
    const int g = lane >> 3, r8 = lane & 7;
    const int a_roff = ((g & 1) << 3) + r8;
    const int a_kh   = g >> 1;
    const int b_roff = ((g >> 1) << 3) + r8;
    const int b_kh   = g & 1;

    uint32_t a_row[2], a_rx[2];
    #pragma unroll
    for (int mt = 0; mt < 2; ++mt) {
        const int row = wm * 32 + mt * 16 + a_roff;
        a_row[mt] = row * 128;
        a_rx[mt] = row & 7;
    }
    uint32_t b_row[2], b_rx[2];
    #pragma unroll
    for (int np = 0; np < 2; ++np) {
        const int row = wn * 32 + np * 16 + b_roff;
        b_row[np] = row * 128;
        b_rx[np] = row & 7;
    }

    float acc[2][4][4];
    uint32_t acch[2][4][2];
    #pragma unroll
    for (int i = 0; i < 2; ++i)
        #pragma unroll
        for (int j = 0; j < 4; ++j) {
            #pragma unroll
            for (int q = 0; q < 4; ++q) acc[i][j][q] = 0.0f;
            acch[i][j][0] = 0u; acch[i][j][1] = 0u;
        }

    const int nst = K / 32;

    #pragma unroll
    for (int p = 0; p < 2; ++p) {
        if (p < nst) {
            const uint32_t tb = sm + p * STAGE_SZ;
            const long k0 = (long)p * 32;
            #pragma unroll
            for (int j = 0; j < 2; ++j) {
                if (doA) cpasync16(tb + soff[j], Asrc + k0 + j * 8);
                if (doB) cpasync16(tb + STAGE_B + soff[j], Bsrc + k0 + j * 8);
            }
        }
        CP_COMMIT();
    }

    int stg = 0;
    for (int s = 0; s < nst; ++s) {
        if (s + 1 < nst) CP_WAIT1(); else CP_WAIT0();
        __syncthreads();

        const uint32_t tb = sm + stg * STAGE_SZ;
        const uint32_t tba = tb, tbb = tb + STAGE_B;

        #pragma unroll
        for (int ks = 0; ks < 2; ++ks) {
            const int ca = ks * 2 + a_kh;
            const int cb = ks * 2 + b_kh;

            // ---- pass 1: Ah x Bh (f32 acc)
            uint32_t Ahr[2][4], Bhr[2][4];
            #pragma unroll
            for (int mt = 0; mt < 2; ++mt)
                LDSM4(Ahr[mt], tba + a_row[mt] + ((ca ^ a_rx[mt]) << 4));
            #pragma unroll
            for (int np = 0; np < 2; ++np)
                LDSM4(Bhr[np], tbb + b_row[np] + ((cb ^ b_rx[np]) << 4));
            #pragma unroll
            for (int mt = 0; mt < 2; ++mt)
                #pragma unroll
                for (int nt = 0; nt < 4; ++nt) {
                    const int np = nt >> 1, s2 = (nt & 1) * 2;
                    MMAF(acc[mt][nt], Ahr[mt], Bhr[np][s2], Bhr[np][s2 + 1]);
                }

            // ---- pass 2: Ah x Bl (f16 acc)
            if (needBlo) {
                uint32_t Blr[2][4];
                #pragma unroll
                for (int np = 0; np < 2; ++np)
                    LDSM4(Blr[np], tbb + b_row[np] + (((cb + 4) ^ b_rx[np]) << 4));
                #pragma unroll
                for (int mt = 0; mt < 2; ++mt)
                    #pragma unroll
                    for (int nt = 0; nt < 4; ++nt) {
                        const int np = nt >> 1, s2 = (nt & 1) * 2;
                        MMAH(acch[mt][nt], Ahr[mt], Blr[np][s2], Blr[np][s2 + 1]);
                    }
            }

            // ---- pass 3: Al x Bh (f16 acc)
            if (needAlo) {
                uint32_t Alr[2][4];
                #pragma unroll
                for (int mt = 0; mt < 2; ++mt)
                    LDSM4(Alr[mt], tba + a_row[mt] + (((ca + 4) ^ a_rx[mt]) << 4));
                #pragma unroll
                for (int mt = 0; mt < 2; ++mt)
                    #pragma unroll
                    for (int nt = 0; nt < 4; ++nt) {
                        const int np = nt >> 1, s2 = (nt & 1) * 2;
                        MMAH(acch[mt][nt], Alr[mt], Bhr[np][s2], Bhr[np][s2 + 1]);
                    }
            }
        }

        if (s + 2 < nst) {
            int ps = stg + 2; if (ps >= NSTAGE) ps -= NSTAGE;
            const uint32_t pb = sm + ps * STAGE_SZ;
            const long k0 = (long)(s + 2) * 32;
            #pragma unroll
            for (int j = 0; j < 2; ++j) {
                if (doA) cpasync16(pb + soff[j], Asrc + k0 + j * 8);
                if (doB) cpasync16(pb + STAGE_B + soff[j], Bsrc + k0 + j * 8);
            }
        }
        CP_COMMIT();

        if (++stg == NSTAGE) stg = 0;
    }

    const int r_in = lane >> 2, c_in = (lane & 3) * 2;
    #pragma unroll
    for (int mt = 0; mt < 2; ++mt) {
        #pragma unroll
        for (int half = 0; half < 2; ++half) {
            const long row = row0 + wm * 32 + mt * 16 + half * 8 + r_in;
            #pragma unroll
            for (int nt = 0; nt < 4; ++nt) {
                const int colg = (int)col0 + wn * 32 + nt * 8 + c_in;
                float v0 = acc[mt][nt][half * 2 + 0];
                float v1 = acc[mt][nt][half * 2 + 1];
                if (PMASK) {
                    float2 cf = __half22float2(*reinterpret_cast<__half2*>(&acch[mt][nt][half]));
                    v0 += cf.x;
                    v1 += cf.y;
                }
                v0 *= alpha;
                v1 *= alpha;
                if (mode == 0) {
                    if (bias) { v0 += bias[colg]; v1 += bias[colg + 1]; }
                    *(float2*)((float*)Cv + coff + row * ldc + colg) = make_float2(v0, v1);
                } else if (mode == 1) {
                    __half h0, l0, h1, l1;
                    split1(v0, h0, l0); split1(v1, h1, l1);
                    __half2 hh; hh.x = h0; hh.y = h1;
                    __half* Ch = (__half*)Cv + coff + row * ldc + colg;
                    *(__half2*)Ch = hh;
                    if (writeLo) {
                        __half2 ll; ll.x = l0; ll.y = l1;
                        *(__half2*)(Ch + cplane) = ll;
                    }
                } else {
                    __half h0, l0, h1, l1;
                    split1(v0, h0, l0); split1(v1, h1, l1);
                    __half* Ch = (__half*)Cv + coff;
                    const long o0 = (long)colg * ldc + row;
                    const long o1 = (long)(colg + 1) * ldc + row;
                    Ch[o0] = h0;
                    Ch[o1] = h1;
                    if (writeLo) {
                        Ch[o0 + cplane] = l0;
                        Ch[o1 + cplane] = l1;
                    }
                }
            }
        }
    }
}

// ---------------------------------------------------------------------------
template <bool WLO>
__global__ void __launch_bounds__(256) split_kernel(const float* __restrict__ in,
                                                    __half* __restrict__ hi, long plane,
                                                    float scale)
{
    const long idx = (long)blockIdx.x * 256 + threadIdx.x;
    float4 v = ((const float4*)in)[idx];
    __half h0, l0, h1, l1, h2, l2, h3, l3;
    split1(v.x * scale, h0, l0); split1(v.y * scale, h1, l1);
    split1(v.z * scale, h2, l2); split1(v.w * scale, h3, l3);
    __half2 a, b;
    a.x = h0; a.y = h1; b.x = h2; b.y = h3;
    ((__half2*)hi)[2 * idx]     = a;
    ((__half2*)hi)[2 * idx + 1] = b;
    if (WLO) {
        __half2 c, d;
        c.x = l0; c.y = l1; d.x = l2; d.y = l3;
        ((__half2*)(hi + plane))[2 * idx]     = c;
        ((__half2*)(hi + plane))[2 * idx + 1] = d;
    }
}

template <bool WLO>
__global__ void __launch_bounds__(256) tsplit_kernel(const float* __restrict__ in,
                                                     __half* __restrict__ outh,
                                                     long plane, int R, int C, float scale)
{
    __shared__ float ts[32][33];
    const int tx = threadIdx.x, ty = threadIdx.y;
    const long zo = (long)blockIdx.z * R * C;
    const int r0 = blockIdx.y * 32, c0 = blockIdx.x * 32;
    #pragma unroll
    for (int i = 0; i < 4; ++i)
        ts[ty + 8 * i][tx] = in[zo + (long)(r0 + ty + 8 * i) * C + c0 + tx];
    __syncthreads();
    #pragma unroll
    for (int i = 0; i < 4; ++i) {
        __half h, l;
        split1(ts[tx][ty + 8 * i] * scale, h, l);
        const long o = zo + (long)(c0 + ty + 8 * i) * R + r0 + tx;
        outh[o] = h;
        if (WLO) outh[o + plane] = l;
    }
}

// fused softmax + head-average: one block per (b, row); loops all 8 heads.
__global__ void __launch_bounds__(256) softmax_avg_kernel(float* __restrict__ avg_out)
{
    const int r = blockIdx.x & (Sq - 1);
    const int b = blockIdx.x >> 11;
    const int tid = threadIdx.x;
    __shared__ float sr[8];

    float avg[8];
    #pragma unroll
    for (int i = 0; i < 8; ++i) avg[i] = 0.0f;

    for (int h = 0; h < Hq; ++h) {
        const long rowo = (((long)b * Hq + h) * Sq + r) * Sq;
        const float* p = g_attn + rowo;

        float v[8];
        float mx = -1e30f;
        #pragma unroll
        for (int i = 0; i < 8; ++i) { v[i] = p[tid + i * 256]; mx = fmaxf(mx, v[i]); }
        #pragma unroll
        for (int o = 16; o > 0; o >>= 1) mx = fmaxf(mx, __shfl_xor_sync(~0u, mx, o));
        if ((tid & 31) == 0) sr[tid >> 5] = mx;
        __syncthreads();
        float m = sr[0];
        #pragma unroll
        for (int i = 1; i < 8; ++i) m = fmaxf(m, sr[i]);
        __syncthreads();
        float s = 0.f;
        #pragma unroll
        for (int i = 0; i < 8; ++i) { v[i] = __expf(v[i] - m); s += v[i]; }
        #pragma unroll
        for (int o = 16; o > 0; o >>= 1) s += __shfl_xor_sync(~0u, s, o);
        if ((tid & 31) == 0) sr[tid >> 5] = s;
        __syncthreads();
        float t = 0.f;
        #pragma unroll
        for (int i = 0; i < 8; ++i) t += sr[i];
        __syncthreads();

        const float inv = 1.0f / t;
        #pragma unroll
        for (int i = 0; i < 8; ++i) {
            const float pv = v[i] * inv;
            avg[i] += pv;
            __half hh, ll;
            split1(pv * 1024.0f, hh, ll);
            g_ps[rowo + tid + i * 256] = hh;
            g_ps[ATTN_PLANE + rowo + tid + i * 256] = ll;
        }
    }

    float* dst = avg_out + ((long)b * Sq + r) * Sq;
    #pragma unroll
    for (int i = 0; i < 8; ++i)
        dst[tid + i * 256] = avg[i] * 0.125f;
}

// ---------------------------------------------------------------------------
extern "C" void kernel_launch(void* const* d_in, const int* in_sizes, int n_in,
                              void* d_out, int out_size)
{
    (void)in_sizes; (void)n_in; (void)out_size;
    const float* Xq = (const float*)d_in[0];
    const float* Xk = (const float*)d_in[1];
    const float* Xv = (const float*)d_in[2];
    const float* Wq = (const float*)d_in[3];
    const float* Wk = (const float*)d_in[4];
    const float* Wv = (const float*)d_in[5];
    const float* Wz = (const float*)d_in[6];
    const float* bz = (const float*)d_in[7];
    float* out = (float*)d_out;
    float* attn_avg = out + (long)Bq * Sq * Dq;

    __half *pxq, *pxk, *pxv, *pwq, *pwk, *pwv, *pwz, *pqs, *pks, *pvt, *pzs, *pps;
    float* pattn;
    cudaGetSymbolAddress((void**)&pxq, g_xq);
    cudaGetSymbolAddress((void**)&pxk, g_xk);
    cudaGetSymbolAddress((void**)&pxv, g_xv);
    cudaGetSymbolAddress((void**)&pwq, g_wqt);
    cudaGetSymbolAddress((void**)&pwk, g_wkt);
    cudaGetSymbolAddress((void**)&pwv, g_wvt);
    cudaGetSymbolAddress((void**)&pwz, g_wzt);
    cudaGetSymbolAddress((void**)&pqs, g_qs);
    cudaGetSymbolAddress((void**)&pks, g_ks);
    cudaGetSymbolAddress((void**)&pvt, g_vts);
    cudaGetSymbolAddress((void**)&pzs, g_zs);
    cudaGetSymbolAddress((void**)&pps, g_ps);
    cudaGetSymbolAddress((void**)&pattn, g_attn);

    cudaFuncSetAttribute(gemm_mma<0>, cudaFuncAttributeMaxDynamicSharedMemorySize, SMEM_SZ);
    cudaFuncSetAttribute(gemm_mma<1>, cudaFuncAttributeMaxDynamicSharedMemorySize, SMEM_SZ);
    cudaFuncSetAttribute(gemm_mma<2>, cudaFuncAttributeMaxDynamicSharedMemorySize, SMEM_SZ);

    const float inv4 = (float)(1.0 / pow((double)Dq, 0.25));

    // 1) convert inputs/weights to fp16 (hi planes only, except Wz which keeps lo)
    {
        int nb = (int)(X_PLANE / 1024);
        split_kernel<false><<<nb, 256>>>(Xq, pxq, X_PLANE, 1.0f);
        split_kernel<false><<<nb, 256>>>(Xk, pxk, X_PLANE, 1.0f);
        split_kernel<false><<<nb, 256>>>(Xv, pxv, X_PLANE, 1.0f);
        dim3 tb(32, 8);
        tsplit_kernel<false><<<dim3(16, 16, 8), tb>>>(Wq, pwq, W_PLANE, Dq, Dq, 16.0f);
        tsplit_kernel<false><<<dim3(16, 16, 8), tb>>>(Wk, pwk, W_PLANE, Dq, Dq, 16.0f);
        tsplit_kernel<false><<<dim3(16, 16, 8), tb>>>(Wv, pwv, W_PLANE, Dq, Dq, 16.0f);
        tsplit_kernel<true><<<dim3(16, 128, 1), tb>>>(Wz, pwz, W_PLANE, Hq * Dq, Dq, 64.0f);
    }

    // 2) projections (TN), single hi-pass. q_s/k_s = 4x true, v_s = 4x v.
    {
        dim3 grid(Dq / 128, Sq / 128, Bq * Hq);
        Off oa = { Hq, SDc, 1, 0 };
        Off ob = { 1, 0, Hq, DDc };
        Off oc = { 1, SDc, 1, 0 };
        gemm_mma<0><<<grid, GTHREADS, SMEM_SZ>>>(pxq, X_PLANE, pwq, W_PLANE, pqs, QK_PLANE,
                                                 Dq, Dq, Dq, Dq, oa, ob, oc, inv4 * 0.25f, nullptr, 1, 0);
        gemm_mma<0><<<grid, GTHREADS, SMEM_SZ>>>(pxk, X_PLANE, pwk, W_PLANE, pks, QK_PLANE,
                                                 Dq, Dq, Dq, Dq, oa, ob, oc, inv4 * 0.25f, nullptr, 1, 0);
        gemm_mma<0><<<grid, GTHREADS, SMEM_SZ>>>(pxv, X_PLANE, pwv, W_PLANE, pvt, QK_PLANE,
                                                 Dq, Dq, Dq, Sq, oa, ob, oc, 0.25f, nullptr, 2, 0);
    }

    // 3) scores (fp32) = q_s.k_s / 16, single hi-pass
    {
        dim3 grid(Sq / 128, Sq / 128, Bq * Hq);
        Off oa = { 1, SDc, 1, 0 };
        Off ob = { 1, SDc, 1, 0 };
        Off oc = { 1, SSc, 1, 0 };
        gemm_mma<0><<<grid, GTHREADS, SMEM_SZ>>>(pqs, QK_PLANE, pks, QK_PLANE, pattn, 0,
                                                 Dq, Dq, Dq, Sq, oa, ob, oc, 1.0f / 16.0f, nullptr, 0, 0);
    }

    // 4) fused softmax + head-average
    softmax_avg_kernel<<<Bq * Sq, 256>>>(attn_avg);

    // 5) z_s = 32*z = (p_s . v_s)/128; keep P_lo.V_hi (PMASK=2)
    {
        dim3 grid(Dq / 128, Sq / 128, Bq * Hq);
        Off oa = { 1, SSc, 1, 0 };
        Off ob = { 1, SDc, 1, 0 };
        Off oc = { Hq, (long)Sq * Hq * Dq, Hq, (long)Dq };
        gemm_mma<2><<<grid, GTHREADS, SMEM_SZ>>>(pps, ATTN_PLANE, pvt, QK_PLANE, pzs, Z_PLANE,
                                                 Sq, Sq, Sq, Hq * Dq, oa, ob, oc, 1.0f / 128.0f, nullptr, 1, 0);
    }

    // 6) out = (z_s . wz_s)/2048 + bz; keep Zh.Wz_lo (PMASK=1)
    {
        dim3 grid(Dq / 128, (Bq * Sq) / 128, 1);
        Off oz = { 1, 0, 1, 0 };
        gemm_mma<1><<<grid, GTHREADS, SMEM_SZ>>>(pzs, Z_PLANE, pwz, W_PLANE, out, 0,
                                                 Hq * Dq, Hq * Dq, Hq * Dq, Dq,
                                                 oz, oz, oz, 1.0f / 2048.0f, bz, 0, 0);
    }
}